// round 11
// baseline (speedup 1.0000x reference)
#include <cuda_runtime.h>
#include <cuda_bf16.h>
#include <math.h>
#include <stdint.h>

#define NB   2
#define NT   2048
#define NMEL 100
#define ND   1024
#define NH   16
#define NDH  64
#define NWIN 512
#define NFF  4096
#define NCD  1024
#define NLAYER 6
#define LNEPS 1e-5f

// ---------------- scratch (device globals) ----------------
__device__ float g_h   [NB*NT*ND];
__device__ float g_qkv [NB*NT*3*ND];
__device__ float g_ta  [NB*NCD];
__device__ float g_tb  [NB*NCD];
__device__ float g_cond[NB*ND];
__device__ float g_ss  [NB*2*ND];
__device__ float g_rc  [NT*(NDH/2)];
__device__ float g_rs  [NT*(NDH/2)];

// split activations (bf16 hi/lo)
__device__ __nv_bfloat16 g_xh  [NB*NT*128];
__device__ __nv_bfloat16 g_xl  [NB*NT*128];
__device__ __nv_bfloat16 g_hn_h[NB*NT*ND];
__device__ __nv_bfloat16 g_hn_l[NB*NT*ND];
__device__ __nv_bfloat16 g_at_h[NB*NT*ND];
__device__ __nv_bfloat16 g_at_l[NB*NT*ND];
__device__ __nv_bfloat16 g_ff_h[NB*NT*NFF];
__device__ __nv_bfloat16 g_ff_l[NB*NT*NFF];

// converted weights: [N][Kpad] bf16 hi/lo
__device__ __nv_bfloat16 c_in_hi  [ND*128];
__device__ __nv_bfloat16 c_in_lo  [ND*128];
__device__ __nv_bfloat16 c_qkv_hi [NLAYER*3*ND*ND];
__device__ __nv_bfloat16 c_qkv_lo [NLAYER*3*ND*ND];
__device__ __nv_bfloat16 c_ao_hi  [NLAYER*ND*ND];
__device__ __nv_bfloat16 c_ao_lo  [NLAYER*ND*ND];
__device__ __nv_bfloat16 c_m1_hi  [NLAYER*NFF*ND];
__device__ __nv_bfloat16 c_m1_lo  [NLAYER*NFF*ND];
__device__ __nv_bfloat16 c_m2_hi  [NLAYER*ND*NFF];
__device__ __nv_bfloat16 c_m2_lo  [NLAYER*ND*NFF];
__device__ __nv_bfloat16 c_out_hi [256*ND];
__device__ __nv_bfloat16 c_out_lo [256*ND];

// ---------------- helpers ----------------
__device__ __forceinline__ uint32_t smem_u32(const void* p){
    uint32_t a;
    asm("{ .reg .u64 t; cvta.to.shared.u64 t, %1; cvt.u32.u64 %0, t; }" : "=r"(a) : "l"(p));
    return a;
}
#define LDSM4(d0,d1,d2,d3,addr) \
    asm volatile("ldmatrix.sync.aligned.m8n8.x4.shared.b16 {%0,%1,%2,%3}, [%4];" \
        : "=r"(d0),"=r"(d1),"=r"(d2),"=r"(d3) : "r"(addr))
#define MMA16816(c, a, b0, b1) \
    asm volatile("mma.sync.aligned.m16n8k16.row.col.f32.bf16.bf16.f32 " \
        "{%0,%1,%2,%3},{%4,%5,%6,%7},{%8,%9},{%0,%1,%2,%3};" \
        : "+f"((c)[0]),"+f"((c)[1]),"+f"((c)[2]),"+f"((c)[3]) \
        : "r"((a)[0]),"r"((a)[1]),"r"((a)[2]),"r"((a)[3]),"r"(b0),"r"(b1))
#define CP_ASYNC16(dst, src) \
    asm volatile("cp.async.cg.shared.global [%0], [%1], 16;" :: "r"(dst), "l"(src))
#define CP_COMMIT() asm volatile("cp.async.commit_group;" ::: "memory")
#define CP_WAIT(n)  asm volatile("cp.async.wait_group %0;" :: "n"(n) : "memory")

__device__ __forceinline__ void split2(float v, __nv_bfloat16& h, __nv_bfloat16& l){
    h = __float2bfloat16_rn(v);
    l = __float2bfloat16_rn(v - __bfloat162float(h));
}
__device__ __forceinline__ uint32_t sw128(uint32_t off){ return off ^ ((off >> 3) & 0x70); }
__device__ __forceinline__ uint64_t smem_desc(uint32_t addr){
    uint64_t d = ((uint64_t)2u << 61) | ((uint64_t)1u << 46) |
                 ((uint64_t)64u << 32) | ((uint64_t)1u << 16);
    return d | (uint64_t)((addr >> 4) & 0x3FFF);
}
#define MBAR_INIT(addr, cnt) \
    asm volatile("mbarrier.init.shared.b64 [%0], %1;" :: "r"(addr), "r"(cnt) : "memory")
#define FENCE_ASYNC() asm volatile("fence.proxy.async.shared::cta;" ::: "memory")

#define TG_IDESC ((1u<<4) | (1u<<7) | (1u<<10) | (32u<<17) | (8u<<24))

// fast exp on FMA pipe (no MUFU): exp(x), rel err ~1e-7, x clamped at -80
__device__ __forceinline__ float fexp(float x){
    x = fmaxf(x, -80.f);
    float t = x * 1.4426950408889634f;
    float fi = rintf(t);
    float f = t - fi;
    float p = 1.5400290e-4f;
    p = fmaf(p, f, 1.33335581e-3f);
    p = fmaf(p, f, 9.61812910e-3f);
    p = fmaf(p, f, 5.55041087e-2f);
    p = fmaf(p, f, 2.40226507e-1f);
    p = fmaf(p, f, 6.93147181e-1f);
    p = fmaf(p, f, 1.0f);
    int e = (int)fi;
    return p * __int_as_float((e + 127) << 23);
}

// ---------------- weight convert: W[K,N] fp32 -> [N,Kpad] bf16 hi/lo ----------------
__global__ void k_wconv(const float* __restrict__ W, __nv_bfloat16* __restrict__ hi,
                        __nv_bfloat16* __restrict__ lo, int K, int N, int Kpad){
    __shared__ float t[32][33];
    int kb = blockIdx.y*32, nb = blockIdx.x*32;
    int x = threadIdx.x, y = threadIdx.y;
    #pragma unroll
    for (int i = 0; i < 32; i += 8){
        int k = kb + y + i, n = nb + x;
        t[y+i][x] = (k < K && n < N) ? W[(size_t)k*N + n] : 0.f;
    }
    __syncthreads();
    #pragma unroll
    for (int i = 0; i < 32; i += 8){
        int n = nb + y + i, k = kb + x;
        if (n < N && k < Kpad){
            float v = t[x][y+i];
            __nv_bfloat16 h, l; split2(v, h, l);
            hi[(size_t)n*Kpad + k] = h;
            lo[(size_t)n*Kpad + k] = l;
        }
    }
}

// ---------------- x split ----------------
__global__ void k_split(const float* __restrict__ X, __nv_bfloat16* __restrict__ Xh,
                        __nv_bfloat16* __restrict__ Xl){
    int i = blockIdx.x*blockDim.x + threadIdx.x;
    int row = i >> 7, col = i & 127;
    float v = (col < NMEL) ? X[(size_t)row*NMEL + col] : 0.f;
    __nv_bfloat16 h, l; split2(v, h, l);
    Xh[i] = h; Xl[i] = l;
}

// ================= main GEMM (unchanged: tcgen05 + fallback) =================
#define TG_SMEM 197632
__global__ __launch_bounds__(256, 1) __cluster_dims__(1,1,1) void k_tgemm(
    const __nv_bfloat16* __restrict__ Ahi, const __nv_bfloat16* __restrict__ Alo, int lda,
    const __nv_bfloat16* __restrict__ Bhi, const __nv_bfloat16* __restrict__ Blo,
    const float* __restrict__ bias, const float* __restrict__ resid,
    float* __restrict__ C, __nv_bfloat16* __restrict__ Chi, __nv_bfloat16* __restrict__ Clo,
    int N, int K, int act)
{
    extern __shared__ char dyn[];
    int tid = threadIdx.x, lane = tid & 31, wid = tid >> 5;
    int m0 = blockIdx.x * 128;
    int nbase = blockIdx.y * 256;

#if defined(__CUDA_ARCH__) && defined(__CUDA_ARCH_FEAT_SM103_ALL)
    __shared__ uint64_t s_mbar[2];
    __shared__ uint32_t s_tmem[1];
    uint32_t sbase = (smem_u32(dyn) + 1023u) & ~1023u;
    char* smp = dyn + (sbase - smem_u32(dyn));
    const uint32_t STG = 98304;

    if (tid == 0){
        MBAR_INIT(smem_u32(&s_mbar[0]), 1);
        MBAR_INIT(smem_u32(&s_mbar[1]), 1);
    }
    if (wid == 0){
        asm volatile("tcgen05.alloc.cta_group::1.sync.aligned.shared::cta.b32 [%0], 256;"
                     :: "r"(smem_u32(s_tmem)) : "memory");
        asm volatile("tcgen05.relinquish_alloc_permit.cta_group::1.sync.aligned;");
    }
    __syncthreads();
    uint32_t tmem = s_tmem[0];
    uint32_t mb[2] = { smem_u32(&s_mbar[0]), smem_u32(&s_mbar[1]) };

    int nch = K >> 6;
    #define TGLOAD(stage, k0) do {                                                 \
        uint32_t s0 = sbase + (stage)*STG;                                         \
        _Pragma("unroll")                                                          \
        for (int j = 0; j < 24; j++){                                              \
            int i = tid + j*256;                                                   \
            uint32_t dst; const __nv_bfloat16* gp;                                 \
            if (i < 2048){                                                         \
                int half = i >> 10, idx = i & 1023;                                \
                int r = idx >> 3, ch = idx & 7;                                    \
                gp = (half ? Alo : Ahi) + (size_t)(m0 + r)*lda + (k0) + ch*8;      \
                dst = s0 + half*16384u + sw128((uint32_t)(r*128 + ch*16));         \
            } else {                                                               \
                int ii = i - 2048;                                                 \
                int half = ii >> 11, idx = ii & 2047;                              \
                int r = idx >> 3, ch = idx & 7;                                    \
                gp = (half ? Blo : Bhi) + (size_t)(nbase + r)*K + (k0) + ch*8;     \
                dst = s0 + 32768u + half*32768u + sw128((uint32_t)(r*128 + ch*16));\
            }                                                                      \
            CP_ASYNC16(dst, gp);                                                   \
        }                                                                          \
    } while(0)

    TGLOAD(0, 0);
    CP_COMMIT();
    uint32_t ph[2] = {0u, 0u};

    for (int c = 0; c < nch; c++){
        if (c + 1 < nch){
            int s2 = (c+1) & 1;
            if (c >= 1){
                asm volatile("{\n\t.reg .pred P;\n\tWL_%=:\n\t"
                    "mbarrier.try_wait.parity.acquire.cta.shared::cta.b64 P, [%0], %1, 0x989680;\n\t"
                    "@P bra.uni WD_%=;\n\tbra.uni WL_%=;\n\tWD_%=:\n\t}"
                    :: "r"(mb[s2]), "r"(ph[s2]) : "memory");
                ph[s2] ^= 1u;
            }
            TGLOAD(s2, (c+1)*64);
            CP_COMMIT();
            CP_WAIT(1);
        } else {
            CP_WAIT(0);
        }
        __syncthreads();
        FENCE_ASYNC();
        if (wid == 0){
            uint32_t pe;
            asm volatile("{\n\t.reg .pred p;\n\telect.sync _|p, 0xFFFFFFFF;\n\tselp.b32 %0, 1, 0, p;\n\t}" : "=r"(pe));
            if (pe){
                uint32_t base = sbase + (c&1)*STG;
                uint64_t ah = smem_desc(base);
                uint64_t al = smem_desc(base + 16384u);
                uint64_t bh = smem_desc(base + 32768u);
                uint64_t bl = smem_desc(base + 65536u);
                #pragma unroll
                for (int ks = 0; ks < 4; ks++){
                    uint32_t a0 = (c > 0 || ks > 0) ? 1u : 0u;
                    asm volatile("{\n\t.reg .pred p;\n\tsetp.ne.u32 p, %5, 0;\n\t"
                        "tcgen05.mma.cta_group::1.kind::f16 [%0], %1, %2, %3, {%4,%4,%4,%4}, p;\n\t}"
                        :: "r"(tmem), "l"(ah + ks*2), "l"(bh + ks*2), "r"(TG_IDESC), "r"(0u), "r"(a0) : "memory");
                    asm volatile("{\n\t.reg .pred p;\n\tsetp.ne.u32 p, %5, 0;\n\t"
                        "tcgen05.mma.cta_group::1.kind::f16 [%0], %1, %2, %3, {%4,%4,%4,%4}, p;\n\t}"
                        :: "r"(tmem), "l"(al + ks*2), "l"(bh + ks*2), "r"(TG_IDESC), "r"(0u), "r"(1u) : "memory");
                    asm volatile("{\n\t.reg .pred p;\n\tsetp.ne.u32 p, %5, 0;\n\t"
                        "tcgen05.mma.cta_group::1.kind::f16 [%0], %1, %2, %3, {%4,%4,%4,%4}, p;\n\t}"
                        :: "r"(tmem), "l"(ah + ks*2), "l"(bl + ks*2), "r"(TG_IDESC), "r"(0u), "r"(1u) : "memory");
                }
                asm volatile("tcgen05.commit.cta_group::1.mbarrier::arrive::one.shared::cluster.b64 [%0];"
                             :: "r"(mb[c&1]) : "memory");
            }
        }
    }
    {
        int s = (nch-1) & 1;
        asm volatile("{\n\t.reg .pred P;\n\tWL_%=:\n\t"
            "mbarrier.try_wait.parity.acquire.cta.shared::cta.b64 P, [%0], %1, 0x989680;\n\t"
            "@P bra.uni WD_%=;\n\tbra.uni WL_%=;\n\tWD_%=:\n\t}"
            :: "r"(mb[s]), "r"(ph[s]) : "memory");
    }
    asm volatile("tcgen05.fence::after_thread_sync;" ::: "memory");

    float* stg = (float*)smp;
    int cb = (wid >> 2) * 128;
    int row = (wid & 3) * 32 + lane;
    #pragma unroll
    for (int r = 0; r < 4; r++){
        uint32_t dreg[32];
        asm volatile("tcgen05.ld.sync.aligned.32x32b.x32.b32 "
            "{%0,%1,%2,%3,%4,%5,%6,%7,%8,%9,%10,%11,%12,%13,%14,%15,"
            "%16,%17,%18,%19,%20,%21,%22,%23,%24,%25,%26,%27,%28,%29,%30,%31}, [%32];"
            : "=r"(dreg[0]),"=r"(dreg[1]),"=r"(dreg[2]),"=r"(dreg[3]),"=r"(dreg[4]),"=r"(dreg[5]),"=r"(dreg[6]),"=r"(dreg[7]),
              "=r"(dreg[8]),"=r"(dreg[9]),"=r"(dreg[10]),"=r"(dreg[11]),"=r"(dreg[12]),"=r"(dreg[13]),"=r"(dreg[14]),"=r"(dreg[15]),
              "=r"(dreg[16]),"=r"(dreg[17]),"=r"(dreg[18]),"=r"(dreg[19]),"=r"(dreg[20]),"=r"(dreg[21]),"=r"(dreg[22]),"=r"(dreg[23]),
              "=r"(dreg[24]),"=r"(dreg[25]),"=r"(dreg[26]),"=r"(dreg[27]),"=r"(dreg[28]),"=r"(dreg[29]),"=r"(dreg[30]),"=r"(dreg[31])
            : "r"(tmem + cb + r*32));
        asm volatile("tcgen05.wait::ld.sync.aligned;" ::: "memory");
        #pragma unroll
        for (int j = 0; j < 32; j++)
            stg[row*261 + cb + r*32 + j] = __uint_as_float(dreg[j]);
    }
    __syncthreads();
    if (wid == 0)
        asm volatile("tcgen05.dealloc.cta_group::1.sync.aligned.b32 %0, 256;" :: "r"(tmem));

    for (int i = tid; i < 8192; i += 256){
        int r = i >> 6, q = (i & 63) * 4;
        int m = m0 + r, n = nbase + q;
        if (n + 3 < N){
            float v0 = stg[r*261 + q]     + bias[n];
            float v1 = stg[r*261 + q + 1] + bias[n+1];
            float v2 = stg[r*261 + q + 2] + bias[n+2];
            float v3 = stg[r*261 + q + 3] + bias[n+3];
            if (act == 1){
                v0 = 0.5f*v0*(1.f + erff(v0*0.70710678118654752f));
                v1 = 0.5f*v1*(1.f + erff(v1*0.70710678118654752f));
                v2 = 0.5f*v2*(1.f + erff(v2*0.70710678118654752f));
                v3 = 0.5f*v3*(1.f + erff(v3*0.70710678118654752f));
            }
            if (Chi){
                __nv_bfloat16 h0,l0,h1,l1,h2,l2,h3,l3;
                split2(v0,h0,l0); split2(v1,h1,l1); split2(v2,h2,l2); split2(v3,h3,l3);
                __nv_bfloat162 hp0; hp0.x=h0; hp0.y=h1;
                __nv_bfloat162 hp1; hp1.x=h2; hp1.y=h3;
                __nv_bfloat162 lp0; lp0.x=l0; lp0.y=l1;
                __nv_bfloat162 lp1; lp1.x=l2; lp1.y=l3;
                *(__nv_bfloat162*)(Chi + (size_t)m*N + n)     = hp0;
                *(__nv_bfloat162*)(Chi + (size_t)m*N + n + 2) = hp1;
                *(__nv_bfloat162*)(Clo + (size_t)m*N + n)     = lp0;
                *(__nv_bfloat162*)(Clo + (size_t)m*N + n + 2) = lp1;
            } else {
                if (resid){
                    float4 rp = *(const float4*)(resid + (size_t)m*N + n);
                    v0 += rp.x; v1 += rp.y; v2 += rp.z; v3 += rp.w;
                }
                float4 o = make_float4(v0, v1, v2, v3);
                *(float4*)(C + (size_t)m*N + n) = o;
            }
        } else if (n < N){
            #pragma unroll
            for (int j = 0; j < 4; j++){
                int nn = n + j;
                if (nn < N){
                    float v = stg[r*261 + q + j] + bias[nn];
                    if (act == 1) v = 0.5f*v*(1.f + erff(v*0.70710678118654752f));
                    if (Chi){
                        __nv_bfloat16 h0,l0; split2(v,h0,l0);
                        Chi[(size_t)m*N + nn] = h0; Clo[(size_t)m*N + nn] = l0;
                    } else {
                        if (resid) v += resid[(size_t)m*N + nn];
                        C[(size_t)m*N + nn] = v;
                    }
                }
            }
        }
    }
    #undef TGLOAD

#else
    #define AST 40
    #define T_ELEM (128*AST)
    #define S_ELEM (4*T_ELEM)
    __nv_bfloat16* sm = (__nv_bfloat16*)dyn;
    uint32_t sb = smem_u32(sm);
    int wm = (wid & 1) * 64;
    int wn = (wid >> 1) * 32;
    int nchunks = K >> 5;

    for (int half = 0; half < 2; half++){
        int n0 = nbase + half*128;
        float acc[16][4];
        #pragma unroll
        for (int i = 0; i < 16; i++){
            acc[i][0]=0.f; acc[i][1]=0.f; acc[i][2]=0.f; acc[i][3]=0.f;
        }
        #define PREFETCH(stage, k0) do {                                               \
            uint32_t s0 = sb + (stage)*(S_ELEM*2);                                     \
            _Pragma("unroll")                                                          \
            for (int j = 0; j < 8; j++){                                               \
                int i = tid + j*256;                                                   \
                int tile = i >> 9, r = (i >> 2) & 127, ch = i & 3;                     \
                const __nv_bfloat16* gp;                                               \
                if      (tile == 0) gp = Ahi + (size_t)(m0+r)*lda + (k0) + ch*8;       \
                else if (tile == 1) gp = Alo + (size_t)(m0+r)*lda + (k0) + ch*8;       \
                else if (tile == 2) gp = Bhi + (size_t)(n0+r)*K   + (k0) + ch*8;       \
                else                gp = Blo + (size_t)(n0+r)*K   + (k0) + ch*8;       \
                uint32_t dst = s0 + tile*(T_ELEM*2) + r*(AST*2) + ch*16;               \
                CP_ASYNC16(dst, gp);                                                   \
            }                                                                          \
        } while(0)
        PREFETCH(0, 0);
        CP_COMMIT();
        for (int c = 0; c < nchunks; c++){
            if (c + 1 < nchunks){
                PREFETCH((c+1)&1, (c+1)*32);
                CP_COMMIT();
                CP_WAIT(1);
            } else CP_WAIT(0);
            __syncthreads();
            __nv_bfloat16* st  = sm + (c&1)*S_ELEM;
            __nv_bfloat16* sAh = st;
            __nv_bfloat16* sAl = st + T_ELEM;
            __nv_bfloat16* sBh = st + 2*T_ELEM;
            __nv_bfloat16* sBl = st + 3*T_ELEM;
            #pragma unroll
            for (int ks = 0; ks < 2; ks++){
                int kb = ks * 16 + (lane >> 4) * 8;
                int rr = lane & 15;
                uint32_t ah[4][4], al[4][4], bfr[2][4];
                #pragma unroll
                for (int mi = 0; mi < 4; mi++){
                    uint32_t ad = smem_u32(&sAh[(wm + mi*16 + rr)*AST + kb]);
                    LDSM4(ah[mi][0], ah[mi][1], ah[mi][2], ah[mi][3], ad);
                }
                #pragma unroll
                for (int mi = 0; mi < 4; mi++){
                    uint32_t ad = smem_u32(&sAl[(wm + mi*16 + rr)*AST + kb]);
                    LDSM4(al[mi][0], al[mi][1], al[mi][2], al[mi][3], ad);
                }
                #pragma unroll
                for (int nj = 0; nj < 2; nj++){
                    uint32_t ad = smem_u32(&sBh[(wn + nj*16 + rr)*AST + kb]);
                    LDSM4(bfr[nj][0], bfr[nj][1], bfr[nj][2], bfr[nj][3], ad);
                }
                #pragma unroll
                for (int mi = 0; mi < 4; mi++)
                    #pragma unroll
                    for (int ni = 0; ni < 4; ni++){
                        uint32_t b0 = bfr[ni>>1][(ni&1)];
                        uint32_t b1 = bfr[ni>>1][(ni&1)+2];
                        MMA16816(acc[mi*4+ni], ah[mi], b0, b1);
                        MMA16816(acc[mi*4+ni], al[mi], b0, b1);
                    }
                #pragma unroll
                for (int nj = 0; nj < 2; nj++){
                    uint32_t ad = smem_u32(&sBl[(wn + nj*16 + rr)*AST + kb]);
                    LDSM4(bfr[nj][0], bfr[nj][1], bfr[nj][2], bfr[nj][3], ad);
                }
                #pragma unroll
                for (int mi = 0; mi < 4; mi++)
                    #pragma unroll
                    for (int ni = 0; ni < 4; ni++){
                        uint32_t b0 = bfr[ni>>1][(ni&1)];
                        uint32_t b1 = bfr[ni>>1][(ni&1)+2];
                        MMA16816(acc[mi*4+ni], ah[mi], b0, b1);
                    }
            }
            __syncthreads();
        }
        #pragma unroll
        for (int mi = 0; mi < 4; mi++){
            #pragma unroll
            for (int ni = 0; ni < 4; ni++){
                float* ac = acc[mi*4+ni];
                int n = n0 + wn + ni*8 + (lane & 3)*2;
                if (n + 1 < N){
                    float b0 = bias[n], b1 = bias[n+1];
                    #pragma unroll
                    for (int hf = 0; hf < 2; hf++){
                        int m = m0 + wm + mi*16 + (lane >> 2) + hf*8;
                        float v0 = ac[hf*2]   + b0;
                        float v1 = ac[hf*2+1] + b1;
                        if (act == 1){
                            v0 = 0.5f*v0*(1.f + erff(v0*0.70710678118654752f));
                            v1 = 0.5f*v1*(1.f + erff(v1*0.70710678118654752f));
                        }
                        if (Chi){
                            __nv_bfloat16 h0,l0,h1,l1;
                            split2(v0,h0,l0); split2(v1,h1,l1);
                            __nv_bfloat162 hp, lp;
                            hp.x=h0; hp.y=h1; lp.x=l0; lp.y=l1;
                            *(__nv_bfloat162*)(Chi + (size_t)m*N + n) = hp;
                            *(__nv_bfloat162*)(Clo + (size_t)m*N + n) = lp;
                        } else {
                            if (resid){
                                float2 rp = *(const float2*)(resid + (size_t)m*N + n);
                                v0 += rp.x; v1 += rp.y;
                            }
                            float2 o = make_float2(v0, v1);
                            *(float2*)(C + (size_t)m*N + n) = o;
                        }
                    }
                } else if (n < N){
                    float b0 = bias[n];
                    #pragma unroll
                    for (int hf = 0; hf < 2; hf++){
                        int m = m0 + wm + mi*16 + (lane >> 2) + hf*8;
                        float v0 = ac[hf*2] + b0;
                        if (act == 1) v0 = 0.5f*v0*(1.f + erff(v0*0.70710678118654752f));
                        if (Chi){
                            __nv_bfloat16 h0,l0; split2(v0,h0,l0);
                            Chi[(size_t)m*N + n] = h0;
                            Clo[(size_t)m*N + n] = l0;
                        } else {
                            if (resid) v0 += resid[(size_t)m*N + n];
                            C[(size_t)m*N + n] = v0;
                        }
                    }
                }
            }
        }
        __syncthreads();
        #undef PREFETCH
    }
#endif
}

// ---------------- timestep embedding features ----------------
__global__ void k_tfeat(const float* __restrict__ t, float* __restrict__ out){
    int i = blockIdx.x*blockDim.x + threadIdx.x;
    if (i >= NB*NCD) return;
    int b = i / NCD, j = i % NCD;
    const int half = NCD/2;
    int idx = (j < half) ? j : (j - half);
    float f   = expf(-9.210340371976184f * (float)idx / (float)half);
    float ang = t[b] * f;
    out[i] = (j < half) ? sinf(ang) : cosf(ang);
}

// ---------------- small GEMM (rows = NB only) ----------------
__global__ __launch_bounds__(256) void k_sgemm2(const float* __restrict__ X,
                                                const float* __restrict__ W,
                                                const float* __restrict__ bias,
                                                float* __restrict__ Y,
                                                int K, int N, int act){
    __shared__ float red[2][4][65];
    int lane = threadIdx.x & 63;
    int slice = threadIdx.x >> 6;
    int n = blockIdx.x*64 + lane;
    int kps = K >> 2;
    float a0 = 0.f, a1 = 0.f;
    if (n < N){
        const float* x0 = X;
        const float* x1 = X + K;
        int k0 = slice*kps, k1 = k0 + kps;
        #pragma unroll 4
        for (int k = k0; k < k1; k++){
            float w = W[(size_t)k*N + n];
            a0 += x0[k]*w; a1 += x1[k]*w;
        }
    }
    red[0][slice][lane] = a0;
    red[1][slice][lane] = a1;
    __syncthreads();
    if (threadIdx.x < 128){
        int bb = threadIdx.x >> 6, l = threadIdx.x & 63;
        float s = red[bb][0][l] + red[bb][1][l] + red[bb][2][l] + red[bb][3][l];
        int nn = blockIdx.x*64 + l;
        if (nn < N){
            s += bias[nn];
            if (act == 1) s = s / (1.f + expf(-s));
            Y[(size_t)bb*N + nn] = s;
        }
    }
}

// ---------------- rope tables ----------------
__global__ void k_rope_tab(){
    int i = blockIdx.x*blockDim.x + threadIdx.x;
    if (i >= NT*(NDH/2)) return;
    int t = i >> 5, j = i & 31;
    float freq = (float)pow(10000.0, -(double)(2*j) / (double)NDH);
    float ang  = (float)t * freq;
    g_rc[i] = cosf(ang);
    g_rs[i] = sinf(ang);
}

// ---------------- LayerNorm (+adaLN), split bf16 hi/lo output ----------------
__global__ __launch_bounds__(256) void k_ln(const float* __restrict__ X,
                                            const float* __restrict__ ss,
                                            __nv_bfloat16* __restrict__ Yh,
                                            __nv_bfloat16* __restrict__ Yl){
    int row = blockIdx.x;
    int b = row / NT;
    const float4* x4 = (const float4*)(X + (size_t)row*ND);
    int tid = threadIdx.x;
    float4 v = x4[tid];
    float s = v.x+v.y+v.z+v.w;
    float q = v.x*v.x+v.y*v.y+v.z*v.z+v.w*v.w;
    #pragma unroll
    for (int o=16;o;o>>=1){ s += __shfl_xor_sync(0xffffffffu,s,o); q += __shfl_xor_sync(0xffffffffu,q,o); }
    __shared__ float shs[8], shq[8];
    __shared__ float smean, srstd;
    int w = tid>>5;
    if ((tid&31)==0){ shs[w]=s; shq[w]=q; }
    __syncthreads();
    if (tid==0){
        float S=0.f,Q=0.f;
        #pragma unroll
        for (int k=0;k<8;k++){ S+=shs[k]; Q+=shq[k]; }
        float mean = S*(1.f/ND);
        float var  = Q*(1.f/ND) - mean*mean;
        smean = mean; srstd = rsqrtf(var + LNEPS);
    }
    __syncthreads();
    float mean = smean, r = srstd;
    int n0 = tid*4;
    float o[4];
    o[0]=(v.x-mean)*r; o[1]=(v.y-mean)*r; o[2]=(v.z-mean)*r; o[3]=(v.w-mean)*r;
    if (ss){
        const float* sc = ss + (size_t)b*2*ND;
        const float* sh = sc + ND;
        #pragma unroll
        for (int j=0;j<4;j++) o[j] = o[j]*(1.f+sc[n0+j]) + sh[n0+j];
    }
    __nv_bfloat16 hh[4], ll[4];
    #pragma unroll
    for (int j=0;j<4;j++) split2(o[j], hh[j], ll[j]);
    *(uint2*)(Yh + (size_t)row*ND + n0) = *(uint2*)hh;
    *(uint2*)(Yl + (size_t)row*ND + n0) = *(uint2*)ll;
}

// ---------------- attention v3: mma.sync bf16 hi/lo, fused rope, poly-exp -------------
// q-tile 128, k-tile 64. 8 warps; warp w owns rows w*16..w*16+15 (full 64 cols).
// QST = 72 halves (64 dims + 8 pad). Dynamic smem: Qh,Ql[128*72], Kh,Kl[64*72], Vh,Vl[64*72].
#define QST 72
#define AT_Q (128*QST)
#define AT_K (64*QST)
#define ATT_SMEM ((2*AT_Q + 4*AT_K)*2)   // bytes = (18432+18432)*2... = 73728
__global__ __launch_bounds__(256) void k_attn(const float* __restrict__ qkv,
                                              __nv_bfloat16* __restrict__ Oh,
                                              __nv_bfloat16* __restrict__ Ol){
    extern __shared__ __nv_bfloat16 smb[];
    __nv_bfloat16* sQh = smb;
    __nv_bfloat16* sQl = smb + AT_Q;
    __nv_bfloat16* sKh = smb + 2*AT_Q;
    __nv_bfloat16* sKl = smb + 2*AT_Q + AT_K;
    __nv_bfloat16* sVh = smb + 2*AT_Q + 2*AT_K;   // transposed: [d][key]
    __nv_bfloat16* sVl = smb + 2*AT_Q + 3*AT_K;
    int qt = blockIdx.x, h = blockIdx.y, b = blockIdx.z;
    int tid = threadIdx.x, lane = tid & 31, w = tid >> 5;
    int q0 = qt * 128;
    int wr = w * 16;
    const float scale = 0.125f;

    // ---- load Q with rope + scale, split hi/lo ----
    for (int i = tid; i < 128*32; i += 256){
        int r = i & 127, jp = i >> 7;        // jp = rope pair index (dims 2jp, 2jp+1)
        int tok = q0 + r;
        size_t g = (((size_t)(b*NT + tok)*3 + 0)*NH + h)*NDH + 2*jp;
        float x1 = qkv[g], x2 = qkv[g+1];
        float cs = g_rc[tok*32 + jp], sn = g_rs[tok*32 + jp];
        float y1 = (x1*cs - x2*sn) * scale;
        float y2 = (x1*sn + x2*cs) * scale;
        __nv_bfloat16 h1,l1,h2,l2;
        split2(y1,h1,l1); split2(y2,h2,l2);
        __nv_bfloat162 hp; hp.x=h1; hp.y=h2;
        __nv_bfloat162 lp; lp.x=l1; lp.y=l2;
        *(__nv_bfloat162*)&sQh[r*QST + 2*jp] = hp;
        *(__nv_bfloat162*)&sQl[r*QST + 2*jp] = lp;
    }
    __syncthreads();

    float accO[8][4];
    #pragma unroll
    for (int i=0;i<8;i++){ accO[i][0]=0.f; accO[i][1]=0.f; accO[i][2]=0.f; accO[i][3]=0.f; }
    float m_[2] = {-1e30f, -1e30f};
    float l_[2] = {0.f, 0.f};

    int ktiles = min(8, 2*qt + 2);
    for (int jt = 0; jt < ktiles; jt++){
        // ---- load K (rope) + V (transposed), split hi/lo ----
        for (int i = tid; i < 64*32; i += 256){
            int r = i & 63, jp = i >> 6;
            int tok = NT - NWIN + jt*64 + r;
            size_t gk = (((size_t)(b*NT + tok)*3 + 1)*NH + h)*NDH + 2*jp;
            float x1 = qkv[gk], x2 = qkv[gk+1];
            float cs = g_rc[tok*32 + jp], sn = g_rs[tok*32 + jp];
            float y1 = x1*cs - x2*sn;
            float y2 = x1*sn + x2*cs;
            __nv_bfloat16 h1,l1,h2,l2;
            split2(y1,h1,l1); split2(y2,h2,l2);
            __nv_bfloat162 hp; hp.x=h1; hp.y=h2;
            __nv_bfloat162 lp; lp.x=l1; lp.y=l2;
            *(__nv_bfloat162*)&sKh[r*QST + 2*jp] = hp;
            *(__nv_bfloat162*)&sKl[r*QST + 2*jp] = lp;
            float v1 = qkv[gk + NH*NDH], v2 = qkv[gk + NH*NDH + 1];
            __nv_bfloat16 vh1,vl1,vh2,vl2;
            split2(v1,vh1,vl1); split2(v2,vh2,vl2);
            sVh[(2*jp)*QST + r]   = vh1;
            sVh[(2*jp+1)*QST + r] = vh2;
            sVl[(2*jp)*QST + r]   = vl1;
            sVl[(2*jp+1)*QST + r] = vl2;
        }
        __syncthreads();

        // ---- scores S (16 rows x 64 cols per warp), 3-way split ----
        float S[8][4];
        #pragma unroll
        for (int i=0;i<8;i++){ S[i][0]=0.f; S[i][1]=0.f; S[i][2]=0.f; S[i][3]=0.f; }
        int kb0 = (lane >> 4) * 8;
        int rr = lane & 15;
        #pragma unroll
        for (int s = 0; s < 4; s++){
            int kb = s*16 + kb0;
            uint32_t qh[4], ql[4], bfr[4][4];
            LDSM4(qh[0],qh[1],qh[2],qh[3], smem_u32(&sQh[(wr + rr)*QST + kb]));
            LDSM4(ql[0],ql[1],ql[2],ql[3], smem_u32(&sQl[(wr + rr)*QST + kb]));
            #pragma unroll
            for (int nj = 0; nj < 4; nj++)
                LDSM4(bfr[nj][0],bfr[nj][1],bfr[nj][2],bfr[nj][3],
                      smem_u32(&sKh[(nj*16 + rr)*QST + kb]));
            #pragma unroll
            for (int ni = 0; ni < 8; ni++){
                uint32_t b0 = bfr[ni>>1][ni&1], b1 = bfr[ni>>1][(ni&1)+2];
                MMA16816(S[ni], qh, b0, b1);
                MMA16816(S[ni], ql, b0, b1);
            }
            #pragma unroll
            for (int nj = 0; nj < 4; nj++)
                LDSM4(bfr[nj][0],bfr[nj][1],bfr[nj][2],bfr[nj][3],
                      smem_u32(&sKl[(nj*16 + rr)*QST + kb]));
            #pragma unroll
            for (int ni = 0; ni < 8; ni++){
                uint32_t b0 = bfr[ni>>1][ni&1], b1 = bfr[ni>>1][(ni&1)+2];
                MMA16816(S[ni], qh, b0, b1);
            }
        }

        // ---- mask (diagonal-straddling tiles only; qt<4) ----
        if (qt < 4 && jt >= 2*qt){
            int r0 = q0 + wr + (lane >> 2);
            int cbase = jt*64 + 2*(lane & 3);
            #pragma unroll
            for (int ni = 0; ni < 8; ni++){
                int cg = cbase + ni*8;
                if (cg     > r0    ) S[ni][0] = -1e30f;
                if (cg + 1 > r0    ) S[ni][1] = -1e30f;
                if (cg     > r0 + 8) S[ni][2] = -1e30f;
                if (cg + 1 > r0 + 8) S[ni][3] = -1e30f;
            }
        }

        // ---- online softmax (rows warp-local; lanes sharing a row differ in lane&3) ----
        float mx0 = -1e30f, mx1 = -1e30f;
        #pragma unroll
        for (int ni = 0; ni < 8; ni++){
            mx0 = fmaxf(mx0, fmaxf(S[ni][0], S[ni][1]));
            mx1 = fmaxf(mx1, fmaxf(S[ni][2], S[ni][3]));
        }
        mx0 = fmaxf(mx0, __shfl_xor_sync(0xffffffffu, mx0, 1));
        mx0 = fmaxf(mx0, __shfl_xor_sync(0xffffffffu, mx0, 2));
        mx1 = fmaxf(mx1, __shfl_xor_sync(0xffffffffu, mx1, 1));
        mx1 = fmaxf(mx1, __shfl_xor_sync(0xffffffffu, mx1, 2));
        float mn0 = fmaxf(m_[0], mx0), mn1 = fmaxf(m_[1], mx1);
        float ls0 = 0.f, ls1 = 0.f;
        #pragma unroll
        for (int ni = 0; ni < 8; ni++){
            S[ni][0] = fexp(S[ni][0] - mn0); ls0 += S[ni][0];
            S[ni][1] = fexp(S[ni][1] - mn0); ls0 += S[ni][1];
            S[ni][2] = fexp(S[ni][2] - mn1); ls1 += S[ni][2];
            S[ni][3] = fexp(S[ni][3] - mn1); ls1 += S[ni][3];
        }
        ls0 += __shfl_xor_sync(0xffffffffu, ls0, 1);
        ls0 += __shfl_xor_sync(0xffffffffu, ls0, 2);
        ls1 += __shfl_xor_sync(0xffffffffu, ls1, 1);
        ls1 += __shfl_xor_sync(0xffffffffu, ls1, 2);
        float al0 = fexp(m_[0] - mn0), al1 = fexp(m_[1] - mn1);
        l_[0] = l_[0]*al0 + ls0;  m_[0] = mn0;
        l_[1] = l_[1]*al1 + ls1;  m_[1] = mn1;
        #pragma unroll
        for (int ni = 0; ni < 8; ni++){
            accO[ni][0] *= al0; accO[ni][1] *= al0;
            accO[ni][2] *= al1; accO[ni][3] *= al1;
        }

        // ---- pack P into A-fragments (hi/lo) ----
        uint32_t pa[8], pb[8], qa[8], qb[8];   // pa/pb: hi c01/c23, qa/qb: lo
        #pragma unroll
        for (int ni = 0; ni < 8; ni++){
            __nv_bfloat16 h0,l0,h1,l1;
            split2(S[ni][0], h0, l0); split2(S[ni][1], h1, l1);
            __nv_bfloat162 hp; hp.x=h0; hp.y=h1;
            __nv_bfloat162 lp; lp.x=l0; lp.y=l1;
            pa[ni] = *(uint32_t*)&hp; qa[ni] = *(uint32_t*)&lp;
            split2(S[ni][2], h0, l0); split2(S[ni][3], h1, l1);
            hp.x=h0; hp.y=h1; lp.x=l0; lp.y=l1;
            pb[ni] = *(uint32_t*)&hp; qb[ni] = *(uint32_t*)&lp;
        }

        // ---- O += P @ V  (3-way split) ----
        #pragma unroll
        for (int s = 0; s < 4; s++){
            int kb = s*16 + kb0;
            uint32_t Ah[4] = { pa[2*s], pb[2*s], pa[2*s+1], pb[2*s+1] };
            uint32_t Al[4] = { qa[2*s], qb[2*s], qa[2*s+1], qb[2*s+1] };
            uint32_t bfr[4][4];
            #pragma unroll
            for (int nj = 0; nj < 4; nj++)
                LDSM4(bfr[nj][0],bfr[nj][1],bfr[nj][2],bfr[nj][3],
                      smem_u32(&sVh[(nj*16 + rr)*QST + kb]));
            #pragma unroll
            for (int ni = 0; ni < 8; ni++){
                uint32_t b0 = bfr[ni>>1][ni&1], b1 = bfr[ni>>1][(ni&1)+2];
                MMA16816(accO[ni], Ah, b0, b1);
                MMA16816(accO[ni], Al, b0, b1);
            }
            #pragma unroll
            for (int nj = 0; nj < 4; nj++)
                LDSM4(bfr[nj][0],bfr[nj][1],bfr[nj][2],bfr[nj][3],
                      smem_u32(&sVl[(nj*16 + rr)*QST + kb]));
            #pragma unroll
            for (int ni = 0; ni < 8; ni++){
                uint32_t b0 = bfr[ni>>1][ni&1], b1 = bfr[ni>>1][(ni&1)+2];
                MMA16816(accO[ni], Ah, b0, b1);
            }
        }
        __syncthreads();
    }

    // ---- epilogue: O / l, split bf16 hi/lo stores ----
    float inv0 = 1.f / l_[0], inv1 = 1.f / l_[1];
    int r0 = q0 + wr + (lane >> 2);
    int cb = 2*(lane & 3);
    #pragma unroll
    for (int ni = 0; ni < 8; ni++){
        int d = ni*8 + cb;
        {
            float v0 = accO[ni][0]*inv0, v1 = accO[ni][1]*inv0;
            __nv_bfloat16 h0,l0,h1,l1;
            split2(v0,h0,l0); split2(v1,h1,l1);
            __nv_bfloat162 hp; hp.x=h0; hp.y=h1;
            __nv_bfloat162 lp; lp.x=l0; lp.y=l1;
            size_t idx = (((size_t)(b*NT + r0))*NH + h)*NDH + d;
            *(__nv_bfloat162*)(Oh + idx) = hp;
            *(__nv_bfloat162*)(Ol + idx) = lp;
        }
        {
            float v0 = accO[ni][2]*inv1, v1 = accO[ni][3]*inv1;
            __nv_bfloat16 h0,l0,h1,l1;
            split2(v0,h0,l0); split2(v1,h1,l1);
            __nv_bfloat162 hp; hp.x=h0; hp.y=h1;
            __nv_bfloat162 lp; lp.x=l0; lp.y=l1;
            size_t idx = (((size_t)(b*NT + r0 + 8))*NH + h)*NDH + d;
            *(__nv_bfloat162*)(Oh + idx) = hp;
            *(__nv_bfloat162*)(Ol + idx) = lp;
        }
    }
}

// ---------------- orchestration ----------------
extern "C" void kernel_launch(void* const* d_in, const int* in_sizes, int n_in,
                              void* d_out, int out_size){
    (void)in_sizes; (void)n_in; (void)out_size;
    const float* x      = (const float*)d_in[0];
    const float* t      = (const float*)d_in[1];
    const float* W_in   = (const float*)d_in[2];
    const float* b_in   = (const float*)d_in[3];
    const float* Wt1    = (const float*)d_in[4];
    const float* bt1    = (const float*)d_in[5];
    const float* Wt2    = (const float*)d_in[6];
    const float* bt2    = (const float*)d_in[7];
    const float* Wcm    = (const float*)d_in[8];
    const float* bcm    = (const float*)d_in[9];
    const float* ada1_W = (const float*)d_in[10];
    const float* ada1_b = (const float*)d_in[11];
    const float* qkv_W  = (const float*)d_in[12];
    const float* qkv_b  = (const float*)d_in[13];
    const float* attno_W= (const float*)d_in[14];
    const float* attno_b= (const float*)d_in[15];
    const float* ada2_W = (const float*)d_in[16];
    const float* ada2_b = (const float*)d_in[17];
    const float* mlp_W1 = (const float*)d_in[18];
    const float* mlp_b1 = (const float*)d_in[19];
    const float* mlp_W2 = (const float*)d_in[20];
    const float* mlp_b2 = (const float*)d_in[21];
    const float* W_out  = (const float*)d_in[22];
    const float* b_out  = (const float*)d_in[23];

    float *p_h,*p_qkv,*p_ta,*p_tb,*p_cond,*p_ss;
    cudaGetSymbolAddress((void**)&p_h,    g_h);
    cudaGetSymbolAddress((void**)&p_qkv,  g_qkv);
    cudaGetSymbolAddress((void**)&p_ta,   g_ta);
    cudaGetSymbolAddress((void**)&p_tb,   g_tb);
    cudaGetSymbolAddress((void**)&p_cond, g_cond);
    cudaGetSymbolAddress((void**)&p_ss,   g_ss);

    __nv_bfloat16 *p_xh,*p_xl,*p_hnh,*p_hnl,*p_ath,*p_atl,*p_ffh,*p_ffl;
    cudaGetSymbolAddress((void**)&p_xh,  g_xh);
    cudaGetSymbolAddress((void**)&p_xl,  g_xl);
    cudaGetSymbolAddress((void**)&p_hnh, g_hn_h);
    cudaGetSymbolAddress((void**)&p_hnl, g_hn_l);
    cudaGetSymbolAddress((void**)&p_ath, g_at_h);
    cudaGetSymbolAddress((void**)&p_atl, g_at_l);
    cudaGetSymbolAddress((void**)&p_ffh, g_ff_h);
    cudaGetSymbolAddress((void**)&p_ffl, g_ff_l);

    __nv_bfloat16 *w_in_h,*w_in_l,*w_qkv_h,*w_qkv_l,*w_ao_h,*w_ao_l;
    __nv_bfloat16 *w_m1_h,*w_m1_l,*w_m2_h,*w_m2_l,*w_out_h,*w_out_l;
    cudaGetSymbolAddress((void**)&w_in_h,  c_in_hi);
    cudaGetSymbolAddress((void**)&w_in_l,  c_in_lo);
    cudaGetSymbolAddress((void**)&w_qkv_h, c_qkv_hi);
    cudaGetSymbolAddress((void**)&w_qkv_l, c_qkv_lo);
    cudaGetSymbolAddress((void**)&w_ao_h,  c_ao_hi);
    cudaGetSymbolAddress((void**)&w_ao_l,  c_ao_lo);
    cudaGetSymbolAddress((void**)&w_m1_h,  c_m1_hi);
    cudaGetSymbolAddress((void**)&w_m1_l,  c_m1_lo);
    cudaGetSymbolAddress((void**)&w_m2_h,  c_m2_hi);
    cudaGetSymbolAddress((void**)&w_m2_l,  c_m2_lo);
    cudaGetSymbolAddress((void**)&w_out_h, c_out_hi);
    cudaGetSymbolAddress((void**)&w_out_l, c_out_lo);

    cudaFuncSetAttribute(k_tgemm, cudaFuncAttributeMaxDynamicSharedMemorySize, TG_SMEM);
    cudaFuncSetAttribute(k_attn,  cudaFuncAttributeMaxDynamicSharedMemorySize, ATT_SMEM);

    const int M = NB*NT;
    dim3 wblk(32, 8);

    // ---- weight conversion ----
    k_wconv<<<dim3(ND/32, 128/32), wblk>>>(W_in,  w_in_h,  w_in_l,  NMEL, ND, 128);
    k_wconv<<<dim3(256/32, ND/32), wblk>>>(W_out, w_out_h, w_out_l, ND, NMEL, ND);
    for (int l = 0; l < NLAYER; l++){
        k_wconv<<<dim3(3*ND/32, ND/32), wblk>>>(qkv_W  + (size_t)l*ND*3*ND, w_qkv_h + (size_t)l*3*ND*ND, w_qkv_l + (size_t)l*3*ND*ND, ND, 3*ND, ND);
        k_wconv<<<dim3(ND/32,   ND/32), wblk>>>(attno_W+ (size_t)l*ND*ND,   w_ao_h  + (size_t)l*ND*ND,   w_ao_l  + (size_t)l*ND*ND,   ND, ND, ND);
        k_wconv<<<dim3(NFF/32,  ND/32), wblk>>>(mlp_W1 + (size_t)l*ND*NFF,  w_m1_h  + (size_t)l*NFF*ND,  w_m1_l  + (size_t)l*NFF*ND,  ND, NFF, ND);
        k_wconv<<<dim3(ND/32,  NFF/32), wblk>>>(mlp_W2 + (size_t)l*NFF*ND,  w_m2_h  + (size_t)l*ND*NFF,  w_m2_l  + (size_t)l*ND*NFF,  NFF, ND, NFF);
    }

    // ---- timestep conditioning ----
    k_tfeat<<<(NB*NCD+255)/256,256>>>(t, p_ta);
    k_sgemm2<<<NCD/64,256>>>(p_ta, Wt1, bt1, p_tb, NCD, NCD, 1);
    k_sgemm2<<<NCD/64,256>>>(p_tb, Wt2, bt2, p_ta, NCD, NCD, 0);
    k_sgemm2<<<ND/64, 256>>>(p_ta, Wcm, bcm, p_cond, NCD, ND, 1);
    k_rope_tab<<<(NT*32+255)/256,256>>>();

    // ---- input projection (padded K = 128) ----
    k_split<<<(M*128)/256, 256>>>(x, p_xh, p_xl);
    k_tgemm<<<dim3(32, 4), 256, TG_SMEM>>>(p_xh, p_xl, 128, w_in_h, w_in_l,
                                           b_in, nullptr, p_h, nullptr, nullptr,
                                           ND, 128, 0);

    for (int l = 0; l < NLAYER; l++){
        k_sgemm2<<<2*ND/64,256>>>(p_cond, ada1_W + (size_t)l*ND*2*ND,
                                  ada1_b + (size_t)l*2*ND, p_ss, ND, 2*ND, 0);
        k_ln<<<M,256>>>(p_h, p_ss, p_hnh, p_hnl);
        k_tgemm<<<dim3(32, 12), 256, TG_SMEM>>>(p_hnh, p_hnl, ND,
                                                w_qkv_h + (size_t)l*3*ND*ND,
                                                w_qkv_l + (size_t)l*3*ND*ND,
                                                qkv_b + (size_t)l*3*ND, nullptr,
                                                p_qkv, nullptr, nullptr,
                                                3*ND, ND, 0);
        k_attn<<<dim3(NT/128, NH, NB), 256, ATT_SMEM>>>(p_qkv, p_ath, p_atl);
        k_tgemm<<<dim3(32, 4), 256, TG_SMEM>>>(p_ath, p_atl, ND,
                                               w_ao_h + (size_t)l*ND*ND,
                                               w_ao_l + (size_t)l*ND*ND,
                                               attno_b + (size_t)l*ND, p_h,
                                               p_h, nullptr, nullptr,
                                               ND, ND, 0);
        k_sgemm2<<<2*ND/64,256>>>(p_cond, ada2_W + (size_t)l*ND*2*ND,
                                  ada2_b + (size_t)l*2*ND, p_ss, ND, 2*ND, 0);
        k_ln<<<M,256>>>(p_h, p_ss, p_hnh, p_hnl);
        k_tgemm<<<dim3(32, 16), 256, TG_SMEM>>>(p_hnh, p_hnl, ND,
                                                w_m1_h + (size_t)l*NFF*ND,
                                                w_m1_l + (size_t)l*NFF*ND,
                                                mlp_b1 + (size_t)l*NFF, nullptr,
                                                nullptr, p_ffh, p_ffl,
                                                NFF, ND, 1);
        k_tgemm<<<dim3(32, 4), 256, TG_SMEM>>>(p_ffh, p_ffl, NFF,
                                               w_m2_h + (size_t)l*ND*NFF,
                                               w_m2_l + (size_t)l*ND*NFF,
                                               mlp_b2 + (size_t)l*ND, p_h,
                                               p_h, nullptr, nullptr,
                                               ND, NFF, 0);
    }

    k_ln<<<M,256>>>(p_h, nullptr, p_hnh, p_hnl);
    k_tgemm<<<dim3(32, 1), 256, TG_SMEM>>>(p_hnh, p_hnl, ND, w_out_h, w_out_l,
                                           b_out, nullptr, (float*)d_out,
                                           nullptr, nullptr, NMEL, ND, 0);
}

// round 12
// speedup vs baseline: 1.2208x; 1.2208x over previous
#include <cuda_runtime.h>
#include <cuda_bf16.h>
#include <math.h>
#include <stdint.h>

#define NB   2
#define NT   2048
#define NMEL 100
#define ND   1024
#define NH   16
#define NDH  64
#define NWIN 512
#define NFF  4096
#define NCD  1024
#define NLAYER 6
#define LNEPS 1e-5f

// ---------------- scratch (device globals) ----------------
__device__ float g_h   [NB*NT*ND];
__device__ float g_qkv [NB*NT*3*ND];
__device__ float g_ta  [NB*NCD];
__device__ float g_tb  [NB*NCD];
__device__ float g_cond[NB*ND];
__device__ float g_ss  [NB*2*ND];
__device__ float g_rc  [NT*(NDH/2)];
__device__ float g_rs  [NT*(NDH/2)];

// split activations (bf16 hi/lo)
__device__ __nv_bfloat16 g_xh  [NB*NT*128];
__device__ __nv_bfloat16 g_xl  [NB*NT*128];
__device__ __nv_bfloat16 g_hn_h[NB*NT*ND];
__device__ __nv_bfloat16 g_hn_l[NB*NT*ND];
__device__ __nv_bfloat16 g_at_h[NB*NT*ND];
__device__ __nv_bfloat16 g_at_l[NB*NT*ND];
__device__ __nv_bfloat16 g_ff_h[NB*NT*NFF];
__device__ __nv_bfloat16 g_ff_l[NB*NT*NFF];

// converted weights: [N][Kpad] bf16 hi/lo
__device__ __nv_bfloat16 c_in_hi  [ND*128];
__device__ __nv_bfloat16 c_in_lo  [ND*128];
__device__ __nv_bfloat16 c_qkv_hi [NLAYER*3*ND*ND];
__device__ __nv_bfloat16 c_qkv_lo [NLAYER*3*ND*ND];
__device__ __nv_bfloat16 c_ao_hi  [NLAYER*ND*ND];
__device__ __nv_bfloat16 c_ao_lo  [NLAYER*ND*ND];
__device__ __nv_bfloat16 c_m1_hi  [NLAYER*NFF*ND];
__device__ __nv_bfloat16 c_m1_lo  [NLAYER*NFF*ND];
__device__ __nv_bfloat16 c_m2_hi  [NLAYER*ND*NFF];
__device__ __nv_bfloat16 c_m2_lo  [NLAYER*ND*NFF];
__device__ __nv_bfloat16 c_out_hi [256*ND];
__device__ __nv_bfloat16 c_out_lo [256*ND];

// ---------------- helpers ----------------
__device__ __forceinline__ uint32_t smem_u32(const void* p){
    uint32_t a;
    asm("{ .reg .u64 t; cvta.to.shared.u64 t, %1; cvt.u32.u64 %0, t; }" : "=r"(a) : "l"(p));
    return a;
}
#define LDSM4(d0,d1,d2,d3,addr) \
    asm volatile("ldmatrix.sync.aligned.m8n8.x4.shared.b16 {%0,%1,%2,%3}, [%4];" \
        : "=r"(d0),"=r"(d1),"=r"(d2),"=r"(d3) : "r"(addr))
#define MMA16816(c, a, b0, b1) \
    asm volatile("mma.sync.aligned.m16n8k16.row.col.f32.bf16.bf16.f32 " \
        "{%0,%1,%2,%3},{%4,%5,%6,%7},{%8,%9},{%0,%1,%2,%3};" \
        : "+f"((c)[0]),"+f"((c)[1]),"+f"((c)[2]),"+f"((c)[3]) \
        : "r"((a)[0]),"r"((a)[1]),"r"((a)[2]),"r"((a)[3]),"r"(b0),"r"(b1))
#define CP_ASYNC16(dst, src) \
    asm volatile("cp.async.cg.shared.global [%0], [%1], 16;" :: "r"(dst), "l"(src))
#define CP_COMMIT() asm volatile("cp.async.commit_group;" ::: "memory")
#define CP_WAIT(n)  asm volatile("cp.async.wait_group %0;" :: "n"(n) : "memory")

__device__ __forceinline__ void split2(float v, __nv_bfloat16& h, __nv_bfloat16& l){
    h = __float2bfloat16_rn(v);
    l = __float2bfloat16_rn(v - __bfloat162float(h));
}
__device__ __forceinline__ uint32_t sw128(uint32_t off){ return off ^ ((off >> 3) & 0x70); }
__device__ __forceinline__ uint64_t smem_desc(uint32_t addr){
    uint64_t d = ((uint64_t)2u << 61) | ((uint64_t)1u << 46) |
                 ((uint64_t)64u << 32) | ((uint64_t)1u << 16);
    return d | (uint64_t)((addr >> 4) & 0x3FFF);
}
#define MBAR_INIT(addr, cnt) \
    asm volatile("mbarrier.init.shared.b64 [%0], %1;" :: "r"(addr), "r"(cnt) : "memory")
#define FENCE_ASYNC() asm volatile("fence.proxy.async.shared::cta;" ::: "memory")

#define TG_IDESC ((1u<<4) | (1u<<7) | (1u<<10) | (32u<<17) | (8u<<24))

// fast exp on FMA pipe (no MUFU): exp(x), rel err ~1e-7, x clamped at -80
__device__ __forceinline__ float fexp(float x){
    x = fmaxf(x, -80.f);
    float t = x * 1.4426950408889634f;
    float fi = rintf(t);
    float f = t - fi;
    float p = 1.5400290e-4f;
    p = fmaf(p, f, 1.33335581e-3f);
    p = fmaf(p, f, 9.61812910e-3f);
    p = fmaf(p, f, 5.55041087e-2f);
    p = fmaf(p, f, 2.40226507e-1f);
    p = fmaf(p, f, 6.93147181e-1f);
    p = fmaf(p, f, 1.0f);
    int e = (int)fi;
    return p * __int_as_float((e + 127) << 23);
}

// ---------------- weight convert: W[K,N] fp32 -> [N,Kpad] bf16 hi/lo ----------------
__global__ void k_wconv(const float* __restrict__ W, __nv_bfloat16* __restrict__ hi,
                        __nv_bfloat16* __restrict__ lo, int K, int N, int Kpad){
    __shared__ float t[32][33];
    int kb = blockIdx.y*32, nb = blockIdx.x*32;
    int x = threadIdx.x, y = threadIdx.y;
    #pragma unroll
    for (int i = 0; i < 32; i += 8){
        int k = kb + y + i, n = nb + x;
        t[y+i][x] = (k < K && n < N) ? W[(size_t)k*N + n] : 0.f;
    }
    __syncthreads();
    #pragma unroll
    for (int i = 0; i < 32; i += 8){
        int n = nb + y + i, k = kb + x;
        if (n < N && k < Kpad){
            float v = t[x][y+i];
            __nv_bfloat16 h, l; split2(v, h, l);
            hi[(size_t)n*Kpad + k] = h;
            lo[(size_t)n*Kpad + k] = l;
        }
    }
}

// ---------------- x split ----------------
__global__ void k_split(const float* __restrict__ X, __nv_bfloat16* __restrict__ Xh,
                        __nv_bfloat16* __restrict__ Xl){
    int i = blockIdx.x*blockDim.x + threadIdx.x;
    int row = i >> 7, col = i & 127;
    float v = (col < NMEL) ? X[(size_t)row*NMEL + col] : 0.f;
    __nv_bfloat16 h, l; split2(v, h, l);
    Xh[i] = h; Xl[i] = l;
}

// ================= main GEMM (unchanged: tcgen05 + fallback) =================
#define TG_SMEM 197632
__global__ __launch_bounds__(256, 1) __cluster_dims__(1,1,1) void k_tgemm(
    const __nv_bfloat16* __restrict__ Ahi, const __nv_bfloat16* __restrict__ Alo, int lda,
    const __nv_bfloat16* __restrict__ Bhi, const __nv_bfloat16* __restrict__ Blo,
    const float* __restrict__ bias, const float* __restrict__ resid,
    float* __restrict__ C, __nv_bfloat16* __restrict__ Chi, __nv_bfloat16* __restrict__ Clo,
    int N, int K, int act)
{
    extern __shared__ char dyn[];
    int tid = threadIdx.x, lane = tid & 31, wid = tid >> 5;
    int m0 = blockIdx.x * 128;
    int nbase = blockIdx.y * 256;

#if defined(__CUDA_ARCH__) && defined(__CUDA_ARCH_FEAT_SM103_ALL)
    __shared__ uint64_t s_mbar[2];
    __shared__ uint32_t s_tmem[1];
    uint32_t sbase = (smem_u32(dyn) + 1023u) & ~1023u;
    char* smp = dyn + (sbase - smem_u32(dyn));
    const uint32_t STG = 98304;

    if (tid == 0){
        MBAR_INIT(smem_u32(&s_mbar[0]), 1);
        MBAR_INIT(smem_u32(&s_mbar[1]), 1);
    }
    if (wid == 0){
        asm volatile("tcgen05.alloc.cta_group::1.sync.aligned.shared::cta.b32 [%0], 256;"
                     :: "r"(smem_u32(s_tmem)) : "memory");
        asm volatile("tcgen05.relinquish_alloc_permit.cta_group::1.sync.aligned;");
    }
    __syncthreads();
    uint32_t tmem = s_tmem[0];
    uint32_t mb[2] = { smem_u32(&s_mbar[0]), smem_u32(&s_mbar[1]) };

    int nch = K >> 6;
    #define TGLOAD(stage, k0) do {                                                 \
        uint32_t s0 = sbase + (stage)*STG;                                         \
        _Pragma("unroll")                                                          \
        for (int j = 0; j < 24; j++){                                              \
            int i = tid + j*256;                                                   \
            uint32_t dst; const __nv_bfloat16* gp;                                 \
            if (i < 2048){                                                         \
                int half = i >> 10, idx = i & 1023;                                \
                int r = idx >> 3, ch = idx & 7;                                    \
                gp = (half ? Alo : Ahi) + (size_t)(m0 + r)*lda + (k0) + ch*8;      \
                dst = s0 + half*16384u + sw128((uint32_t)(r*128 + ch*16));         \
            } else {                                                               \
                int ii = i - 2048;                                                 \
                int half = ii >> 11, idx = ii & 2047;                              \
                int r = idx >> 3, ch = idx & 7;                                    \
                gp = (half ? Blo : Bhi) + (size_t)(nbase + r)*K + (k0) + ch*8;     \
                dst = s0 + 32768u + half*32768u + sw128((uint32_t)(r*128 + ch*16));\
            }                                                                      \
            CP_ASYNC16(dst, gp);                                                   \
        }                                                                          \
    } while(0)

    TGLOAD(0, 0);
    CP_COMMIT();
    uint32_t ph[2] = {0u, 0u};

    for (int c = 0; c < nch; c++){
        if (c + 1 < nch){
            int s2 = (c+1) & 1;
            if (c >= 1){
                asm volatile("{\n\t.reg .pred P;\n\tWL_%=:\n\t"
                    "mbarrier.try_wait.parity.acquire.cta.shared::cta.b64 P, [%0], %1, 0x989680;\n\t"
                    "@P bra.uni WD_%=;\n\tbra.uni WL_%=;\n\tWD_%=:\n\t}"
                    :: "r"(mb[s2]), "r"(ph[s2]) : "memory");
                ph[s2] ^= 1u;
            }
            TGLOAD(s2, (c+1)*64);
            CP_COMMIT();
            CP_WAIT(1);
        } else {
            CP_WAIT(0);
        }
        __syncthreads();
        FENCE_ASYNC();
        if (wid == 0){
            uint32_t pe;
            asm volatile("{\n\t.reg .pred p;\n\telect.sync _|p, 0xFFFFFFFF;\n\tselp.b32 %0, 1, 0, p;\n\t}" : "=r"(pe));
            if (pe){
                uint32_t base = sbase + (c&1)*STG;
                uint64_t ah = smem_desc(base);
                uint64_t al = smem_desc(base + 16384u);
                uint64_t bh = smem_desc(base + 32768u);
                uint64_t bl = smem_desc(base + 65536u);
                #pragma unroll
                for (int ks = 0; ks < 4; ks++){
                    uint32_t a0 = (c > 0 || ks > 0) ? 1u : 0u;
                    asm volatile("{\n\t.reg .pred p;\n\tsetp.ne.u32 p, %5, 0;\n\t"
                        "tcgen05.mma.cta_group::1.kind::f16 [%0], %1, %2, %3, {%4,%4,%4,%4}, p;\n\t}"
                        :: "r"(tmem), "l"(ah + ks*2), "l"(bh + ks*2), "r"(TG_IDESC), "r"(0u), "r"(a0) : "memory");
                    asm volatile("{\n\t.reg .pred p;\n\tsetp.ne.u32 p, %5, 0;\n\t"
                        "tcgen05.mma.cta_group::1.kind::f16 [%0], %1, %2, %3, {%4,%4,%4,%4}, p;\n\t}"
                        :: "r"(tmem), "l"(al + ks*2), "l"(bh + ks*2), "r"(TG_IDESC), "r"(0u), "r"(1u) : "memory");
                    asm volatile("{\n\t.reg .pred p;\n\tsetp.ne.u32 p, %5, 0;\n\t"
                        "tcgen05.mma.cta_group::1.kind::f16 [%0], %1, %2, %3, {%4,%4,%4,%4}, p;\n\t}"
                        :: "r"(tmem), "l"(ah + ks*2), "l"(bl + ks*2), "r"(TG_IDESC), "r"(0u), "r"(1u) : "memory");
                }
                asm volatile("tcgen05.commit.cta_group::1.mbarrier::arrive::one.shared::cluster.b64 [%0];"
                             :: "r"(mb[c&1]) : "memory");
            }
        }
    }
    {
        int s = (nch-1) & 1;
        asm volatile("{\n\t.reg .pred P;\n\tWL_%=:\n\t"
            "mbarrier.try_wait.parity.acquire.cta.shared::cta.b64 P, [%0], %1, 0x989680;\n\t"
            "@P bra.uni WD_%=;\n\tbra.uni WL_%=;\n\tWD_%=:\n\t}"
            :: "r"(mb[s]), "r"(ph[s]) : "memory");
    }
    asm volatile("tcgen05.fence::after_thread_sync;" ::: "memory");

    float* stg = (float*)smp;
    int cb = (wid >> 2) * 128;
    int row = (wid & 3) * 32 + lane;
    #pragma unroll
    for (int r = 0; r < 4; r++){
        uint32_t dreg[32];
        asm volatile("tcgen05.ld.sync.aligned.32x32b.x32.b32 "
            "{%0,%1,%2,%3,%4,%5,%6,%7,%8,%9,%10,%11,%12,%13,%14,%15,"
            "%16,%17,%18,%19,%20,%21,%22,%23,%24,%25,%26,%27,%28,%29,%30,%31}, [%32];"
            : "=r"(dreg[0]),"=r"(dreg[1]),"=r"(dreg[2]),"=r"(dreg[3]),"=r"(dreg[4]),"=r"(dreg[5]),"=r"(dreg[6]),"=r"(dreg[7]),
              "=r"(dreg[8]),"=r"(dreg[9]),"=r"(dreg[10]),"=r"(dreg[11]),"=r"(dreg[12]),"=r"(dreg[13]),"=r"(dreg[14]),"=r"(dreg[15]),
              "=r"(dreg[16]),"=r"(dreg[17]),"=r"(dreg[18]),"=r"(dreg[19]),"=r"(dreg[20]),"=r"(dreg[21]),"=r"(dreg[22]),"=r"(dreg[23]),
              "=r"(dreg[24]),"=r"(dreg[25]),"=r"(dreg[26]),"=r"(dreg[27]),"=r"(dreg[28]),"=r"(dreg[29]),"=r"(dreg[30]),"=r"(dreg[31])
            : "r"(tmem + cb + r*32));
        asm volatile("tcgen05.wait::ld.sync.aligned;" ::: "memory");
        #pragma unroll
        for (int j = 0; j < 32; j++)
            stg[row*261 + cb + r*32 + j] = __uint_as_float(dreg[j]);
    }
    __syncthreads();
    if (wid == 0)
        asm volatile("tcgen05.dealloc.cta_group::1.sync.aligned.b32 %0, 256;" :: "r"(tmem));

    for (int i = tid; i < 8192; i += 256){
        int r = i >> 6, q = (i & 63) * 4;
        int m = m0 + r, n = nbase + q;
        if (n + 3 < N){
            float v0 = stg[r*261 + q]     + bias[n];
            float v1 = stg[r*261 + q + 1] + bias[n+1];
            float v2 = stg[r*261 + q + 2] + bias[n+2];
            float v3 = stg[r*261 + q + 3] + bias[n+3];
            if (act == 1){
                v0 = 0.5f*v0*(1.f + erff(v0*0.70710678118654752f));
                v1 = 0.5f*v1*(1.f + erff(v1*0.70710678118654752f));
                v2 = 0.5f*v2*(1.f + erff(v2*0.70710678118654752f));
                v3 = 0.5f*v3*(1.f + erff(v3*0.70710678118654752f));
            }
            if (Chi){
                __nv_bfloat16 h0,l0,h1,l1,h2,l2,h3,l3;
                split2(v0,h0,l0); split2(v1,h1,l1); split2(v2,h2,l2); split2(v3,h3,l3);
                __nv_bfloat162 hp0; hp0.x=h0; hp0.y=h1;
                __nv_bfloat162 hp1; hp1.x=h2; hp1.y=h3;
                __nv_bfloat162 lp0; lp0.x=l0; lp0.y=l1;
                __nv_bfloat162 lp1; lp1.x=l2; lp1.y=l3;
                *(__nv_bfloat162*)(Chi + (size_t)m*N + n)     = hp0;
                *(__nv_bfloat162*)(Chi + (size_t)m*N + n + 2) = hp1;
                *(__nv_bfloat162*)(Clo + (size_t)m*N + n)     = lp0;
                *(__nv_bfloat162*)(Clo + (size_t)m*N + n + 2) = lp1;
            } else {
                if (resid){
                    float4 rp = *(const float4*)(resid + (size_t)m*N + n);
                    v0 += rp.x; v1 += rp.y; v2 += rp.z; v3 += rp.w;
                }
                float4 o = make_float4(v0, v1, v2, v3);
                *(float4*)(C + (size_t)m*N + n) = o;
            }
        } else if (n < N){
            #pragma unroll
            for (int j = 0; j < 4; j++){
                int nn = n + j;
                if (nn < N){
                    float v = stg[r*261 + q + j] + bias[nn];
                    if (act == 1) v = 0.5f*v*(1.f + erff(v*0.70710678118654752f));
                    if (Chi){
                        __nv_bfloat16 h0,l0; split2(v,h0,l0);
                        Chi[(size_t)m*N + nn] = h0; Clo[(size_t)m*N + nn] = l0;
                    } else {
                        if (resid) v += resid[(size_t)m*N + nn];
                        C[(size_t)m*N + nn] = v;
                    }
                }
            }
        }
    }
    #undef TGLOAD

#else
    #define AST 40
    #define T_ELEM (128*AST)
    #define S_ELEM (4*T_ELEM)
    __nv_bfloat16* sm = (__nv_bfloat16*)dyn;
    uint32_t sb = smem_u32(sm);
    int wm = (wid & 1) * 64;
    int wn = (wid >> 1) * 32;
    int nchunks = K >> 5;

    for (int half = 0; half < 2; half++){
        int n0 = nbase + half*128;
        float acc[16][4];
        #pragma unroll
        for (int i = 0; i < 16; i++){
            acc[i][0]=0.f; acc[i][1]=0.f; acc[i][2]=0.f; acc[i][3]=0.f;
        }
        #define PREFETCH(stage, k0) do {                                               \
            uint32_t s0 = sb + (stage)*(S_ELEM*2);                                     \
            _Pragma("unroll")                                                          \
            for (int j = 0; j < 8; j++){                                               \
                int i = tid + j*256;                                                   \
                int tile = i >> 9, r = (i >> 2) & 127, ch = i & 3;                     \
                const __nv_bfloat16* gp;                                               \
                if      (tile == 0) gp = Ahi + (size_t)(m0+r)*lda + (k0) + ch*8;       \
                else if (tile == 1) gp = Alo + (size_t)(m0+r)*lda + (k0) + ch*8;       \
                else if (tile == 2) gp = Bhi + (size_t)(n0+r)*K   + (k0) + ch*8;       \
                else                gp = Blo + (size_t)(n0+r)*K   + (k0) + ch*8;       \
                uint32_t dst = s0 + tile*(T_ELEM*2) + r*(AST*2) + ch*16;               \
                CP_ASYNC16(dst, gp);                                                   \
            }                                                                          \
        } while(0)
        PREFETCH(0, 0);
        CP_COMMIT();
        for (int c = 0; c < nchunks; c++){
            if (c + 1 < nchunks){
                PREFETCH((c+1)&1, (c+1)*32);
                CP_COMMIT();
                CP_WAIT(1);
            } else CP_WAIT(0);
            __syncthreads();
            __nv_bfloat16* st  = sm + (c&1)*S_ELEM;
            __nv_bfloat16* sAh = st;
            __nv_bfloat16* sAl = st + T_ELEM;
            __nv_bfloat16* sBh = st + 2*T_ELEM;
            __nv_bfloat16* sBl = st + 3*T_ELEM;
            #pragma unroll
            for (int ks = 0; ks < 2; ks++){
                int kb = ks * 16 + (lane >> 4) * 8;
                int rr = lane & 15;
                uint32_t ah[4][4], al[4][4], bfr[2][4];
                #pragma unroll
                for (int mi = 0; mi < 4; mi++){
                    uint32_t ad = smem_u32(&sAh[(wm + mi*16 + rr)*AST + kb]);
                    LDSM4(ah[mi][0], ah[mi][1], ah[mi][2], ah[mi][3], ad);
                }
                #pragma unroll
                for (int mi = 0; mi < 4; mi++){
                    uint32_t ad = smem_u32(&sAl[(wm + mi*16 + rr)*AST + kb]);
                    LDSM4(al[mi][0], al[mi][1], al[mi][2], al[mi][3], ad);
                }
                #pragma unroll
                for (int nj = 0; nj < 2; nj++){
                    uint32_t ad = smem_u32(&sBh[(wn + nj*16 + rr)*AST + kb]);
                    LDSM4(bfr[nj][0], bfr[nj][1], bfr[nj][2], bfr[nj][3], ad);
                }
                #pragma unroll
                for (int mi = 0; mi < 4; mi++)
                    #pragma unroll
                    for (int ni = 0; ni < 4; ni++){
                        uint32_t b0 = bfr[ni>>1][(ni&1)];
                        uint32_t b1 = bfr[ni>>1][(ni&1)+2];
                        MMA16816(acc[mi*4+ni], ah[mi], b0, b1);
                        MMA16816(acc[mi*4+ni], al[mi], b0, b1);
                    }
                #pragma unroll
                for (int nj = 0; nj < 2; nj++){
                    uint32_t ad = smem_u32(&sBl[(wn + nj*16 + rr)*AST + kb]);
                    LDSM4(bfr[nj][0], bfr[nj][1], bfr[nj][2], bfr[nj][3], ad);
                }
                #pragma unroll
                for (int mi = 0; mi < 4; mi++)
                    #pragma unroll
                    for (int ni = 0; ni < 4; ni++){
                        uint32_t b0 = bfr[ni>>1][(ni&1)];
                        uint32_t b1 = bfr[ni>>1][(ni&1)+2];
                        MMA16816(acc[mi*4+ni], ah[mi], b0, b1);
                    }
            }
            __syncthreads();
        }
        #pragma unroll
        for (int mi = 0; mi < 4; mi++){
            #pragma unroll
            for (int ni = 0; ni < 4; ni++){
                float* ac = acc[mi*4+ni];
                int n = n0 + wn + ni*8 + (lane & 3)*2;
                if (n + 1 < N){
                    float b0 = bias[n], b1 = bias[n+1];
                    #pragma unroll
                    for (int hf = 0; hf < 2; hf++){
                        int m = m0 + wm + mi*16 + (lane >> 2) + hf*8;
                        float v0 = ac[hf*2]   + b0;
                        float v1 = ac[hf*2+1] + b1;
                        if (act == 1){
                            v0 = 0.5f*v0*(1.f + erff(v0*0.70710678118654752f));
                            v1 = 0.5f*v1*(1.f + erff(v1*0.70710678118654752f));
                        }
                        if (Chi){
                            __nv_bfloat16 h0,l0,h1,l1;
                            split2(v0,h0,l0); split2(v1,h1,l1);
                            __nv_bfloat162 hp, lp;
                            hp.x=h0; hp.y=h1; lp.x=l0; lp.y=l1;
                            *(__nv_bfloat162*)(Chi + (size_t)m*N + n) = hp;
                            *(__nv_bfloat162*)(Clo + (size_t)m*N + n) = lp;
                        } else {
                            if (resid){
                                float2 rp = *(const float2*)(resid + (size_t)m*N + n);
                                v0 += rp.x; v1 += rp.y;
                            }
                            float2 o = make_float2(v0, v1);
                            *(float2*)(C + (size_t)m*N + n) = o;
                        }
                    }
                } else if (n < N){
                    float b0 = bias[n];
                    #pragma unroll
                    for (int hf = 0; hf < 2; hf++){
                        int m = m0 + wm + mi*16 + (lane >> 2) + hf*8;
                        float v0 = ac[hf*2] + b0;
                        if (act == 1) v0 = 0.5f*v0*(1.f + erff(v0*0.70710678118654752f));
                        if (Chi){
                            __nv_bfloat16 h0,l0; split2(v0,h0,l0);
                            Chi[(size_t)m*N + n] = h0;
                            Clo[(size_t)m*N + n] = l0;
                        } else {
                            if (resid) v0 += resid[(size_t)m*N + n];
                            C[(size_t)m*N + n] = v0;
                        }
                    }
                }
            }
        }
        __syncthreads();
        #undef PREFETCH
    }
#endif
}

// ---------------- timestep embedding features ----------------
__global__ void k_tfeat(const float* __restrict__ t, float* __restrict__ out){
    int i = blockIdx.x*blockDim.x + threadIdx.x;
    if (i >= NB*NCD) return;
    int b = i / NCD, j = i % NCD;
    const int half = NCD/2;
    int idx = (j < half) ? j : (j - half);
    float f   = expf(-9.210340371976184f * (float)idx / (float)half);
    float ang = t[b] * f;
    out[i] = (j < half) ? sinf(ang) : cosf(ang);
}

// ---------------- small GEMM (rows = NB only) ----------------
__global__ __launch_bounds__(256) void k_sgemm2(const float* __restrict__ X,
                                                const float* __restrict__ W,
                                                const float* __restrict__ bias,
                                                float* __restrict__ Y,
                                                int K, int N, int act){
    __shared__ float red[2][4][65];
    int lane = threadIdx.x & 63;
    int slice = threadIdx.x >> 6;
    int n = blockIdx.x*64 + lane;
    int kps = K >> 2;
    float a0 = 0.f, a1 = 0.f;
    if (n < N){
        const float* x0 = X;
        const float* x1 = X + K;
        int k0 = slice*kps, k1 = k0 + kps;
        #pragma unroll 4
        for (int k = k0; k < k1; k++){
            float w = W[(size_t)k*N + n];
            a0 += x0[k]*w; a1 += x1[k]*w;
        }
    }
    red[0][slice][lane] = a0;
    red[1][slice][lane] = a1;
    __syncthreads();
    if (threadIdx.x < 128){
        int bb = threadIdx.x >> 6, l = threadIdx.x & 63;
        float s = red[bb][0][l] + red[bb][1][l] + red[bb][2][l] + red[bb][3][l];
        int nn = blockIdx.x*64 + l;
        if (nn < N){
            s += bias[nn];
            if (act == 1) s = s / (1.f + expf(-s));
            Y[(size_t)bb*N + nn] = s;
        }
    }
}

// ---------------- rope tables ----------------
__global__ void k_rope_tab(){
    int i = blockIdx.x*blockDim.x + threadIdx.x;
    if (i >= NT*(NDH/2)) return;
    int t = i >> 5, j = i & 31;
    float freq = (float)pow(10000.0, -(double)(2*j) / (double)NDH);
    float ang  = (float)t * freq;
    g_rc[i] = cosf(ang);
    g_rs[i] = sinf(ang);
}

// ---------------- LayerNorm (+adaLN), split bf16 hi/lo output ----------------
__global__ __launch_bounds__(256) void k_ln(const float* __restrict__ X,
                                            const float* __restrict__ ss,
                                            __nv_bfloat16* __restrict__ Yh,
                                            __nv_bfloat16* __restrict__ Yl){
    int row = blockIdx.x;
    int b = row / NT;
    const float4* x4 = (const float4*)(X + (size_t)row*ND);
    int tid = threadIdx.x;
    float4 v = x4[tid];
    float s = v.x+v.y+v.z+v.w;
    float q = v.x*v.x+v.y*v.y+v.z*v.z+v.w*v.w;
    #pragma unroll
    for (int o=16;o;o>>=1){ s += __shfl_xor_sync(0xffffffffu,s,o); q += __shfl_xor_sync(0xffffffffu,q,o); }
    __shared__ float shs[8], shq[8];
    __shared__ float smean, srstd;
    int w = tid>>5;
    if ((tid&31)==0){ shs[w]=s; shq[w]=q; }
    __syncthreads();
    if (tid==0){
        float S=0.f,Q=0.f;
        #pragma unroll
        for (int k=0;k<8;k++){ S+=shs[k]; Q+=shq[k]; }
        float mean = S*(1.f/ND);
        float var  = Q*(1.f/ND) - mean*mean;
        smean = mean; srstd = rsqrtf(var + LNEPS);
    }
    __syncthreads();
    float mean = smean, r = srstd;
    int n0 = tid*4;
    float o[4];
    o[0]=(v.x-mean)*r; o[1]=(v.y-mean)*r; o[2]=(v.z-mean)*r; o[3]=(v.w-mean)*r;
    if (ss){
        const float* sc = ss + (size_t)b*2*ND;
        const float* sh = sc + ND;
        #pragma unroll
        for (int j=0;j<4;j++) o[j] = o[j]*(1.f+sc[n0+j]) + sh[n0+j];
    }
    __nv_bfloat16 hh[4], ll[4];
    #pragma unroll
    for (int j=0;j<4;j++) split2(o[j], hh[j], ll[j]);
    *(uint2*)(Yh + (size_t)row*ND + n0) = *(uint2*)hh;
    *(uint2*)(Yl + (size_t)row*ND + n0) = *(uint2*)ll;
}

// ---------------- attention v3b: mma.sync bf16 hi/lo, fused rope, poly-exp ------------
// q-tile 128, k-tile 64. 8 warps; warp w owns rows w*16..w*16+15 (full 64 cols).
// COALESCED loaders: lane indexes the dim-pair (jp), warp-uniform token row.
#define QST 72
#define AT_Q (128*QST)
#define AT_K (64*QST)
#define ATT_SMEM ((2*AT_Q + 4*AT_K)*2)
__global__ __launch_bounds__(256) void k_attn(const float* __restrict__ qkv,
                                              __nv_bfloat16* __restrict__ Oh,
                                              __nv_bfloat16* __restrict__ Ol){
    extern __shared__ __nv_bfloat16 smb[];
    __nv_bfloat16* sQh = smb;
    __nv_bfloat16* sQl = smb + AT_Q;
    __nv_bfloat16* sKh = smb + 2*AT_Q;
    __nv_bfloat16* sKl = smb + 2*AT_Q + AT_K;
    __nv_bfloat16* sVh = smb + 2*AT_Q + 2*AT_K;   // transposed: [d][key]
    __nv_bfloat16* sVl = smb + 2*AT_Q + 3*AT_K;
    int qt = blockIdx.x, h = blockIdx.y, b = blockIdx.z;
    int tid = threadIdx.x, lane = tid & 31, w = tid >> 5;
    int q0 = qt * 128;
    int wr = w * 16;
    const float scale = 0.125f;

    // ---- load Q with rope + scale, split hi/lo (coalesced: jp = lane) ----
    for (int i = tid; i < 128*32; i += 256){
        int jp = i & 31, r = i >> 5;
        int tok = q0 + r;
        size_t g = (((size_t)(b*NT + tok)*3 + 0)*NH + h)*NDH + 2*jp;
        float x1 = qkv[g], x2 = qkv[g+1];
        float cs = g_rc[tok*32 + jp], sn = g_rs[tok*32 + jp];
        float y1 = (x1*cs - x2*sn) * scale;
        float y2 = (x1*sn + x2*cs) * scale;
        __nv_bfloat16 h1,l1,h2,l2;
        split2(y1,h1,l1); split2(y2,h2,l2);
        __nv_bfloat162 hp; hp.x=h1; hp.y=h2;
        __nv_bfloat162 lp; lp.x=l1; lp.y=l2;
        *(__nv_bfloat162*)&sQh[r*QST + 2*jp] = hp;
        *(__nv_bfloat162*)&sQl[r*QST + 2*jp] = lp;
    }
    __syncthreads();

    float accO[8][4];
    #pragma unroll
    for (int i=0;i<8;i++){ accO[i][0]=0.f; accO[i][1]=0.f; accO[i][2]=0.f; accO[i][3]=0.f; }
    float m_[2] = {-1e30f, -1e30f};
    float l_[2] = {0.f, 0.f};

    int ktiles = min(8, 2*qt + 2);
    for (int jt = 0; jt < ktiles; jt++){
        // ---- load K (rope) + V (transposed), split hi/lo (coalesced: jp = lane) ----
        for (int i = tid; i < 64*32; i += 256){
            int jp = i & 31, r = i >> 5;
            int tok = NT - NWIN + jt*64 + r;
            size_t gk = (((size_t)(b*NT + tok)*3 + 1)*NH + h)*NDH + 2*jp;
            float x1 = qkv[gk], x2 = qkv[gk+1];
            float cs = g_rc[tok*32 + jp], sn = g_rs[tok*32 + jp];
            float y1 = x1*cs - x2*sn;
            float y2 = x1*sn + x2*cs;
            __nv_bfloat16 h1,l1,h2,l2;
            split2(y1,h1,l1); split2(y2,h2,l2);
            __nv_bfloat162 hp; hp.x=h1; hp.y=h2;
            __nv_bfloat162 lp; lp.x=l1; lp.y=l2;
            *(__nv_bfloat162*)&sKh[r*QST + 2*jp] = hp;
            *(__nv_bfloat162*)&sKl[r*QST + 2*jp] = lp;
            float v1 = qkv[gk + NH*NDH], v2 = qkv[gk + NH*NDH + 1];
            __nv_bfloat16 vh1,vl1,vh2,vl2;
            split2(v1,vh1,vl1); split2(v2,vh2,vl2);
            sVh[(2*jp)*QST + r]   = vh1;
            sVh[(2*jp+1)*QST + r] = vh2;
            sVl[(2*jp)*QST + r]   = vl1;
            sVl[(2*jp+1)*QST + r] = vl2;
        }
        __syncthreads();

        // ---- scores S (16 rows x 64 cols per warp), 3-way split ----
        float S[8][4];
        #pragma unroll
        for (int i=0;i<8;i++){ S[i][0]=0.f; S[i][1]=0.f; S[i][2]=0.f; S[i][3]=0.f; }
        int kb0 = (lane >> 4) * 8;
        int rr = lane & 15;
        #pragma unroll
        for (int s = 0; s < 4; s++){
            int kb = s*16 + kb0;
            uint32_t qh[4], ql[4], bfr[4][4];
            LDSM4(qh[0],qh[1],qh[2],qh[3], smem_u32(&sQh[(wr + rr)*QST + kb]));
            LDSM4(ql[0],ql[1],ql[2],ql[3], smem_u32(&sQl[(wr + rr)*QST + kb]));
            #pragma unroll
            for (int nj = 0; nj < 4; nj++)
                LDSM4(bfr[nj][0],bfr[nj][1],bfr[nj][2],bfr[nj][3],
                      smem_u32(&sKh[(nj*16 + rr)*QST + kb]));
            #pragma unroll
            for (int ni = 0; ni < 8; ni++){
                uint32_t b0 = bfr[ni>>1][ni&1], b1 = bfr[ni>>1][(ni&1)+2];
                MMA16816(S[ni], qh, b0, b1);
                MMA16816(S[ni], ql, b0, b1);
            }
            #pragma unroll
            for (int nj = 0; nj < 4; nj++)
                LDSM4(bfr[nj][0],bfr[nj][1],bfr[nj][2],bfr[nj][3],
                      smem_u32(&sKl[(nj*16 + rr)*QST + kb]));
            #pragma unroll
            for (int ni = 0; ni < 8; ni++){
                uint32_t b0 = bfr[ni>>1][ni&1], b1 = bfr[ni>>1][(ni&1)+2];
                MMA16816(S[ni], qh, b0, b1);
            }
        }

        // ---- mask (diagonal-straddling tiles only; qt<4) ----
        if (qt < 4 && jt >= 2*qt){
            int r0 = q0 + wr + (lane >> 2);
            int cbase = jt*64 + 2*(lane & 3);
            #pragma unroll
            for (int ni = 0; ni < 8; ni++){
                int cg = cbase + ni*8;
                if (cg     > r0    ) S[ni][0] = -1e30f;
                if (cg + 1 > r0    ) S[ni][1] = -1e30f;
                if (cg     > r0 + 8) S[ni][2] = -1e30f;
                if (cg + 1 > r0 + 8) S[ni][3] = -1e30f;
            }
        }

        // ---- online softmax ----
        float mx0 = -1e30f, mx1 = -1e30f;
        #pragma unroll
        for (int ni = 0; ni < 8; ni++){
            mx0 = fmaxf(mx0, fmaxf(S[ni][0], S[ni][1]));
            mx1 = fmaxf(mx1, fmaxf(S[ni][2], S[ni][3]));
        }
        mx0 = fmaxf(mx0, __shfl_xor_sync(0xffffffffu, mx0, 1));
        mx0 = fmaxf(mx0, __shfl_xor_sync(0xffffffffu, mx0, 2));
        mx1 = fmaxf(mx1, __shfl_xor_sync(0xffffffffu, mx1, 1));
        mx1 = fmaxf(mx1, __shfl_xor_sync(0xffffffffu, mx1, 2));
        float mn0 = fmaxf(m_[0], mx0), mn1 = fmaxf(m_[1], mx1);
        float ls0 = 0.f, ls1 = 0.f;
        #pragma unroll
        for (int ni = 0; ni < 8; ni++){
            S[ni][0] = fexp(S[ni][0] - mn0); ls0 += S[ni][0];
            S[ni][1] = fexp(S[ni][1] - mn0); ls0 += S[ni][1];
            S[ni][2] = fexp(S[ni][2] - mn1); ls1 += S[ni][2];
            S[ni][3] = fexp(S[ni][3] - mn1); ls1 += S[ni][3];
        }
        ls0 += __shfl_xor_sync(0xffffffffu, ls0, 1);
        ls0 += __shfl_xor_sync(0xffffffffu, ls0, 2);
        ls1 += __shfl_xor_sync(0xffffffffu, ls1, 1);
        ls1 += __shfl_xor_sync(0xffffffffu, ls1, 2);
        float al0 = fexp(m_[0] - mn0), al1 = fexp(m_[1] - mn1);
        l_[0] = l_[0]*al0 + ls0;  m_[0] = mn0;
        l_[1] = l_[1]*al1 + ls1;  m_[1] = mn1;
        #pragma unroll
        for (int ni = 0; ni < 8; ni++){
            accO[ni][0] *= al0; accO[ni][1] *= al0;
            accO[ni][2] *= al1; accO[ni][3] *= al1;
        }

        // ---- pack P into A-fragments (hi/lo) ----
        uint32_t pa[8], pb[8], qa[8], qb[8];
        #pragma unroll
        for (int ni = 0; ni < 8; ni++){
            __nv_bfloat16 h0,l0,h1,l1;
            split2(S[ni][0], h0, l0); split2(S[ni][1], h1, l1);
            __nv_bfloat162 hp; hp.x=h0; hp.y=h1;
            __nv_bfloat162 lp; lp.x=l0; lp.y=l1;
            pa[ni] = *(uint32_t*)&hp; qa[ni] = *(uint32_t*)&lp;
            split2(S[ni][2], h0, l0); split2(S[ni][3], h1, l1);
            hp.x=h0; hp.y=h1; lp.x=l0; lp.y=l1;
            pb[ni] = *(uint32_t*)&hp; qb[ni] = *(uint32_t*)&lp;
        }

        // ---- O += P @ V  (3-way split) ----
        #pragma unroll
        for (int s = 0; s < 4; s++){
            int kb = s*16 + kb0;
            uint32_t Ah[4] = { pa[2*s], pb[2*s], pa[2*s+1], pb[2*s+1] };
            uint32_t Al[4] = { qa[2*s], qb[2*s], qa[2*s+1], qb[2*s+1] };
            uint32_t bfr[4][4];
            #pragma unroll
            for (int nj = 0; nj < 4; nj++)
                LDSM4(bfr[nj][0],bfr[nj][1],bfr[nj][2],bfr[nj][3],
                      smem_u32(&sVh[(nj*16 + rr)*QST + kb]));
            #pragma unroll
            for (int ni = 0; ni < 8; ni++){
                uint32_t b0 = bfr[ni>>1][ni&1], b1 = bfr[ni>>1][(ni&1)+2];
                MMA16816(accO[ni], Ah, b0, b1);
                MMA16816(accO[ni], Al, b0, b1);
            }
            #pragma unroll
            for (int nj = 0; nj < 4; nj++)
                LDSM4(bfr[nj][0],bfr[nj][1],bfr[nj][2],bfr[nj][3],
                      smem_u32(&sVl[(nj*16 + rr)*QST + kb]));
            #pragma unroll
            for (int ni = 0; ni < 8; ni++){
                uint32_t b0 = bfr[ni>>1][ni&1], b1 = bfr[ni>>1][(ni&1)+2];
                MMA16816(accO[ni], Ah, b0, b1);
            }
        }
        __syncthreads();
    }

    // ---- epilogue: O / l, split bf16 hi/lo stores ----
    float inv0 = 1.f / l_[0], inv1 = 1.f / l_[1];
    int r0 = q0 + wr + (lane >> 2);
    int cb = 2*(lane & 3);
    #pragma unroll
    for (int ni = 0; ni < 8; ni++){
        int d = ni*8 + cb;
        {
            float v0 = accO[ni][0]*inv0, v1 = accO[ni][1]*inv0;
            __nv_bfloat16 h0,l0,h1,l1;
            split2(v0,h0,l0); split2(v1,h1,l1);
            __nv_bfloat162 hp; hp.x=h0; hp.y=h1;
            __nv_bfloat162 lp; lp.x=l0; lp.y=l1;
            size_t idx = (((size_t)(b*NT + r0))*NH + h)*NDH + d;
            *(__nv_bfloat162*)(Oh + idx) = hp;
            *(__nv_bfloat162*)(Ol + idx) = lp;
        }
        {
            float v0 = accO[ni][2]*inv1, v1 = accO[ni][3]*inv1;
            __nv_bfloat16 h0,l0,h1,l1;
            split2(v0,h0,l0); split2(v1,h1,l1);
            __nv_bfloat162 hp; hp.x=h0; hp.y=h1;
            __nv_bfloat162 lp; lp.x=l0; lp.y=l1;
            size_t idx = (((size_t)(b*NT + r0 + 8))*NH + h)*NDH + d;
            *(__nv_bfloat162*)(Oh + idx) = hp;
            *(__nv_bfloat162*)(Ol + idx) = lp;
        }
    }
}

// ---------------- orchestration ----------------
extern "C" void kernel_launch(void* const* d_in, const int* in_sizes, int n_in,
                              void* d_out, int out_size){
    (void)in_sizes; (void)n_in; (void)out_size;
    const float* x      = (const float*)d_in[0];
    const float* t      = (const float*)d_in[1];
    const float* W_in   = (const float*)d_in[2];
    const float* b_in   = (const float*)d_in[3];
    const float* Wt1    = (const float*)d_in[4];
    const float* bt1    = (const float*)d_in[5];
    const float* Wt2    = (const float*)d_in[6];
    const float* bt2    = (const float*)d_in[7];
    const float* Wcm    = (const float*)d_in[8];
    const float* bcm    = (const float*)d_in[9];
    const float* ada1_W = (const float*)d_in[10];
    const float* ada1_b = (const float*)d_in[11];
    const float* qkv_W  = (const float*)d_in[12];
    const float* qkv_b  = (const float*)d_in[13];
    const float* attno_W= (const float*)d_in[14];
    const float* attno_b= (const float*)d_in[15];
    const float* ada2_W = (const float*)d_in[16];
    const float* ada2_b = (const float*)d_in[17];
    const float* mlp_W1 = (const float*)d_in[18];
    const float* mlp_b1 = (const float*)d_in[19];
    const float* mlp_W2 = (const float*)d_in[20];
    const float* mlp_b2 = (const float*)d_in[21];
    const float* W_out  = (const float*)d_in[22];
    const float* b_out  = (const float*)d_in[23];

    float *p_h,*p_qkv,*p_ta,*p_tb,*p_cond,*p_ss;
    cudaGetSymbolAddress((void**)&p_h,    g_h);
    cudaGetSymbolAddress((void**)&p_qkv,  g_qkv);
    cudaGetSymbolAddress((void**)&p_ta,   g_ta);
    cudaGetSymbolAddress((void**)&p_tb,   g_tb);
    cudaGetSymbolAddress((void**)&p_cond, g_cond);
    cudaGetSymbolAddress((void**)&p_ss,   g_ss);

    __nv_bfloat16 *p_xh,*p_xl,*p_hnh,*p_hnl,*p_ath,*p_atl,*p_ffh,*p_ffl;
    cudaGetSymbolAddress((void**)&p_xh,  g_xh);
    cudaGetSymbolAddress((void**)&p_xl,  g_xl);
    cudaGetSymbolAddress((void**)&p_hnh, g_hn_h);
    cudaGetSymbolAddress((void**)&p_hnl, g_hn_l);
    cudaGetSymbolAddress((void**)&p_ath, g_at_h);
    cudaGetSymbolAddress((void**)&p_atl, g_at_l);
    cudaGetSymbolAddress((void**)&p_ffh, g_ff_h);
    cudaGetSymbolAddress((void**)&p_ffl, g_ff_l);

    __nv_bfloat16 *w_in_h,*w_in_l,*w_qkv_h,*w_qkv_l,*w_ao_h,*w_ao_l;
    __nv_bfloat16 *w_m1_h,*w_m1_l,*w_m2_h,*w_m2_l,*w_out_h,*w_out_l;
    cudaGetSymbolAddress((void**)&w_in_h,  c_in_hi);
    cudaGetSymbolAddress((void**)&w_in_l,  c_in_lo);
    cudaGetSymbolAddress((void**)&w_qkv_h, c_qkv_hi);
    cudaGetSymbolAddress((void**)&w_qkv_l, c_qkv_lo);
    cudaGetSymbolAddress((void**)&w_ao_h,  c_ao_hi);
    cudaGetSymbolAddress((void**)&w_ao_l,  c_ao_lo);
    cudaGetSymbolAddress((void**)&w_m1_h,  c_m1_hi);
    cudaGetSymbolAddress((void**)&w_m1_l,  c_m1_lo);
    cudaGetSymbolAddress((void**)&w_m2_h,  c_m2_hi);
    cudaGetSymbolAddress((void**)&w_m2_l,  c_m2_lo);
    cudaGetSymbolAddress((void**)&w_out_h, c_out_hi);
    cudaGetSymbolAddress((void**)&w_out_l, c_out_lo);

    cudaFuncSetAttribute(k_tgemm, cudaFuncAttributeMaxDynamicSharedMemorySize, TG_SMEM);
    cudaFuncSetAttribute(k_attn,  cudaFuncAttributeMaxDynamicSharedMemorySize, ATT_SMEM);

    const int M = NB*NT;
    dim3 wblk(32, 8);

    // ---- weight conversion ----
    k_wconv<<<dim3(ND/32, 128/32), wblk>>>(W_in,  w_in_h,  w_in_l,  NMEL, ND, 128);
    k_wconv<<<dim3(256/32, ND/32), wblk>>>(W_out, w_out_h, w_out_l, ND, NMEL, ND);
    for (int l = 0; l < NLAYER; l++){
        k_wconv<<<dim3(3*ND/32, ND/32), wblk>>>(qkv_W  + (size_t)l*ND*3*ND, w_qkv_h + (size_t)l*3*ND*ND, w_qkv_l + (size_t)l*3*ND*ND, ND, 3*ND, ND);
        k_wconv<<<dim3(ND/32,   ND/32), wblk>>>(attno_W+ (size_t)l*ND*ND,   w_ao_h  + (size_t)l*ND*ND,   w_ao_l  + (size_t)l*ND*ND,   ND, ND, ND);
        k_wconv<<<dim3(NFF/32,  ND/32), wblk>>>(mlp_W1 + (size_t)l*ND*NFF,  w_m1_h  + (size_t)l*NFF*ND,  w_m1_l  + (size_t)l*NFF*ND,  ND, NFF, ND);
        k_wconv<<<dim3(ND/32,  NFF/32), wblk>>>(mlp_W2 + (size_t)l*NFF*ND,  w_m2_h  + (size_t)l*ND*NFF,  w_m2_l  + (size_t)l*ND*NFF,  NFF, ND, NFF);
    }

    // ---- timestep conditioning ----
    k_tfeat<<<(NB*NCD+255)/256,256>>>(t, p_ta);
    k_sgemm2<<<NCD/64,256>>>(p_ta, Wt1, bt1, p_tb, NCD, NCD, 1);
    k_sgemm2<<<NCD/64,256>>>(p_tb, Wt2, bt2, p_ta, NCD, NCD, 0);
    k_sgemm2<<<ND/64, 256>>>(p_ta, Wcm, bcm, p_cond, NCD, ND, 1);
    k_rope_tab<<<(NT*32+255)/256,256>>>();

    // ---- input projection (padded K = 128) ----
    k_split<<<(M*128)/256, 256>>>(x, p_xh, p_xl);
    k_tgemm<<<dim3(32, 4), 256, TG_SMEM>>>(p_xh, p_xl, 128, w_in_h, w_in_l,
                                           b_in, nullptr, p_h, nullptr, nullptr,
                                           ND, 128, 0);

    for (int l = 0; l < NLAYER; l++){
        k_sgemm2<<<2*ND/64,256>>>(p_cond, ada1_W + (size_t)l*ND*2*ND,
                                  ada1_b + (size_t)l*2*ND, p_ss, ND, 2*ND, 0);
        k_ln<<<M,256>>>(p_h, p_ss, p_hnh, p_hnl);
        k_tgemm<<<dim3(32, 12), 256, TG_SMEM>>>(p_hnh, p_hnl, ND,
                                                w_qkv_h + (size_t)l*3*ND*ND,
                                                w_qkv_l + (size_t)l*3*ND*ND,
                                                qkv_b + (size_t)l*3*ND, nullptr,
                                                p_qkv, nullptr, nullptr,
                                                3*ND, ND, 0);
        k_attn<<<dim3(NT/128, NH, NB), 256, ATT_SMEM>>>(p_qkv, p_ath, p_atl);
        k_tgemm<<<dim3(32, 4), 256, TG_SMEM>>>(p_ath, p_atl, ND,
                                               w_ao_h + (size_t)l*ND*ND,
                                               w_ao_l + (size_t)l*ND*ND,
                                               attno_b + (size_t)l*ND, p_h,
                                               p_h, nullptr, nullptr,
                                               ND, ND, 0);
        k_sgemm2<<<2*ND/64,256>>>(p_cond, ada2_W + (size_t)l*ND*2*ND,
                                  ada2_b + (size_t)l*2*ND, p_ss, ND, 2*ND, 0);
        k_ln<<<M,256>>>(p_h, p_ss, p_hnh, p_hnl);
        k_tgemm<<<dim3(32, 16), 256, TG_SMEM>>>(p_hnh, p_hnl, ND,
                                                w_m1_h + (size_t)l*NFF*ND,
                                                w_m1_l + (size_t)l*NFF*ND,
                                                mlp_b1 + (size_t)l*NFF, nullptr,
                                                nullptr, p_ffh, p_ffl,
                                                NFF, ND, 1);
        k_tgemm<<<dim3(32, 4), 256, TG_SMEM>>>(p_ffh, p_ffl, NFF,
                                               w_m2_h + (size_t)l*ND*NFF,
                                               w_m2_l + (size_t)l*ND*NFF,
                                               mlp_b2 + (size_t)l*ND, p_h,
                                               p_h, nullptr, nullptr,
                                               ND, NFF, 0);
    }

    k_ln<<<M,256>>>(p_h, nullptr, p_hnh, p_hnl);
    k_tgemm<<<dim3(32, 1), 256, TG_SMEM>>>(p_hnh, p_hnl, ND, w_out_h, w_out_l,
                                           b_out, nullptr, (float*)d_out,
                                           nullptr, nullptr, NMEL, ND, 0);
}

// round 15
// speedup vs baseline: 1.3738x; 1.1254x over previous
#include <cuda_runtime.h>
#include <cuda_bf16.h>
#include <math.h>
#include <stdint.h>

#define NB   2
#define NT   2048
#define NMEL 100
#define ND   1024
#define NH   16
#define NDH  64
#define NWIN 512
#define NFF  4096
#define NCD  1024
#define NLAYER 6
#define LNEPS 1e-5f

// ---------------- scratch (device globals) ----------------
__device__ float g_h   [NB*NT*ND];
__device__ float g_qkv [NB*NT*3*ND];
__device__ float g_ta  [NB*NCD];
__device__ float g_tb  [NB*NCD];
__device__ float g_cond[NB*ND];
__device__ float g_ss1 [NLAYER*NB*2*ND];
__device__ float g_ss2 [NLAYER*NB*2*ND];
__device__ float g_rc  [NT*(NDH/2)];
__device__ float g_rs  [NT*(NDH/2)];

// split activations (bf16 hi/lo)
__device__ __nv_bfloat16 g_xh  [NB*NT*128];
__device__ __nv_bfloat16 g_xl  [NB*NT*128];
__device__ __nv_bfloat16 g_hn_h[NB*NT*ND];
__device__ __nv_bfloat16 g_hn_l[NB*NT*ND];
__device__ __nv_bfloat16 g_at_h[NB*NT*ND];
__device__ __nv_bfloat16 g_at_l[NB*NT*ND];
__device__ __nv_bfloat16 g_ff_h[NB*NT*NFF];
__device__ __nv_bfloat16 g_ff_l[NB*NT*NFF];

// converted weights: [N][Kpad] bf16 hi/lo
__device__ __nv_bfloat16 c_in_hi  [ND*128];
__device__ __nv_bfloat16 c_in_lo  [ND*128];
__device__ __nv_bfloat16 c_qkv_hi [NLAYER*3*ND*ND];
__device__ __nv_bfloat16 c_qkv_lo [NLAYER*3*ND*ND];
__device__ __nv_bfloat16 c_ao_hi  [NLAYER*ND*ND];
__device__ __nv_bfloat16 c_ao_lo  [NLAYER*ND*ND];
__device__ __nv_bfloat16 c_m1_hi  [NLAYER*NFF*ND];
__device__ __nv_bfloat16 c_m1_lo  [NLAYER*NFF*ND];
__device__ __nv_bfloat16 c_m2_hi  [NLAYER*ND*NFF];
__device__ __nv_bfloat16 c_m2_lo  [NLAYER*ND*NFF];
__device__ __nv_bfloat16 c_out_hi [256*ND];
__device__ __nv_bfloat16 c_out_lo [256*ND];

// ---------------- helpers ----------------
__device__ __forceinline__ uint32_t smem_u32(const void* p){
    uint32_t a;
    asm("{ .reg .u64 t; cvta.to.shared.u64 t, %1; cvt.u32.u64 %0, t; }" : "=r"(a) : "l"(p));
    return a;
}
#define LDSM4(d0,d1,d2,d3,addr) \
    asm volatile("ldmatrix.sync.aligned.m8n8.x4.shared.b16 {%0,%1,%2,%3}, [%4];" \
        : "=r"(d0),"=r"(d1),"=r"(d2),"=r"(d3) : "r"(addr))
#define MMA16816(c, a, b0, b1) \
    asm volatile("mma.sync.aligned.m16n8k16.row.col.f32.bf16.bf16.f32 " \
        "{%0,%1,%2,%3},{%4,%5,%6,%7},{%8,%9},{%0,%1,%2,%3};" \
        : "+f"((c)[0]),"+f"((c)[1]),"+f"((c)[2]),"+f"((c)[3]) \
        : "r"((a)[0]),"r"((a)[1]),"r"((a)[2]),"r"((a)[3]),"r"(b0),"r"(b1))
#define CP_ASYNC16(dst, src) \
    asm volatile("cp.async.cg.shared.global [%0], [%1], 16;" :: "r"(dst), "l"(src))
#define CP_COMMIT() asm volatile("cp.async.commit_group;" ::: "memory")
#define CP_WAIT(n)  asm volatile("cp.async.wait_group %0;" :: "n"(n) : "memory")

__device__ __forceinline__ void split2(float v, __nv_bfloat16& h, __nv_bfloat16& l){
    h = __float2bfloat16_rn(v);
    l = __float2bfloat16_rn(v - __bfloat162float(h));
}
__device__ __forceinline__ uint32_t sw128(uint32_t off){ return off ^ ((off >> 3) & 0x70); }
__device__ __forceinline__ uint64_t smem_desc(uint32_t addr){
    uint64_t d = ((uint64_t)2u << 61) | ((uint64_t)1u << 46) |
                 ((uint64_t)64u << 32) | ((uint64_t)1u << 16);
    return d | (uint64_t)((addr >> 4) & 0x3FFF);
}
#define MBAR_INIT(addr, cnt) \
    asm volatile("mbarrier.init.shared.b64 [%0], %1;" :: "r"(addr), "r"(cnt) : "memory")
#define FENCE_ASYNC() asm volatile("fence.proxy.async.shared::cta;" ::: "memory")

#define TG_IDESC ((1u<<4) | (1u<<7) | (1u<<10) | (32u<<17) | (8u<<24))

// fast exp on FMA pipe (no MUFU)
__device__ __forceinline__ float fexp(float x){
    x = fmaxf(x, -80.f);
    float t = x * 1.4426950408889634f;
    float fi = rintf(t);
    float f = t - fi;
    float p = 1.5400290e-4f;
    p = fmaf(p, f, 1.33335581e-3f);
    p = fmaf(p, f, 9.61812910e-3f);
    p = fmaf(p, f, 5.55041087e-2f);
    p = fmaf(p, f, 2.40226507e-1f);
    p = fmaf(p, f, 6.93147181e-1f);
    p = fmaf(p, f, 1.0f);
    int e = (int)fi;
    return p * __int_as_float((e + 127) << 23);
}

// ---------------- weight convert (batched over layers via blockIdx.z) ----------------
__global__ void k_wconv(const float* __restrict__ W, __nv_bfloat16* __restrict__ hi,
                        __nv_bfloat16* __restrict__ lo, int K, int N, int Kpad,
                        size_t strideW, size_t strideC){
    __shared__ float t[32][33];
    int l = blockIdx.z;
    const float* Wl = W + (size_t)l*strideW;
    __nv_bfloat16* hil = hi + (size_t)l*strideC;
    __nv_bfloat16* lol = lo + (size_t)l*strideC;
    int kb = blockIdx.y*32, nb = blockIdx.x*32;
    int x = threadIdx.x, y = threadIdx.y;
    #pragma unroll
    for (int i = 0; i < 32; i += 8){
        int k = kb + y + i, n = nb + x;
        t[y+i][x] = (k < K && n < N) ? Wl[(size_t)k*N + n] : 0.f;
    }
    __syncthreads();
    #pragma unroll
    for (int i = 0; i < 32; i += 8){
        int n = nb + y + i, k = kb + x;
        if (n < N && k < Kpad){
            float v = t[x][y+i];
            __nv_bfloat16 h, l2; split2(v, h, l2);
            hil[(size_t)n*Kpad + k] = h;
            lol[(size_t)n*Kpad + k] = l2;
        }
    }
}

// ---------------- x split ----------------
__global__ void k_split(const float* __restrict__ X, __nv_bfloat16* __restrict__ Xh,
                        __nv_bfloat16* __restrict__ Xl){
    int i = blockIdx.x*blockDim.x + threadIdx.x;
    int row = i >> 7, col = i & 127;
    float v = (col < NMEL) ? X[(size_t)row*NMEL + col] : 0.f;
    __nv_bfloat16 h, l; split2(v, h, l);
    Xh[i] = h; Xl[i] = l;
}

// ================= main GEMM (unchanged: tcgen05 + fallback) =================
#define TG_SMEM 197632
__global__ __launch_bounds__(256, 1) __cluster_dims__(1,1,1) void k_tgemm(
    const __nv_bfloat16* __restrict__ Ahi, const __nv_bfloat16* __restrict__ Alo, int lda,
    const __nv_bfloat16* __restrict__ Bhi, const __nv_bfloat16* __restrict__ Blo,
    const float* __restrict__ bias, const float* __restrict__ resid,
    float* __restrict__ C, __nv_bfloat16* __restrict__ Chi, __nv_bfloat16* __restrict__ Clo,
    int N, int K, int act)
{
    extern __shared__ char dyn[];
    int tid = threadIdx.x, lane = tid & 31, wid = tid >> 5;
    int m0 = blockIdx.x * 128;
    int nbase = blockIdx.y * 256;

#if defined(__CUDA_ARCH__) && defined(__CUDA_ARCH_FEAT_SM103_ALL)
    __shared__ uint64_t s_mbar[2];
    __shared__ uint32_t s_tmem[1];
    uint32_t sbase = (smem_u32(dyn) + 1023u) & ~1023u;
    char* smp = dyn + (sbase - smem_u32(dyn));
    const uint32_t STG = 98304;

    if (tid == 0){
        MBAR_INIT(smem_u32(&s_mbar[0]), 1);
        MBAR_INIT(smem_u32(&s_mbar[1]), 1);
    }
    if (wid == 0){
        asm volatile("tcgen05.alloc.cta_group::1.sync.aligned.shared::cta.b32 [%0], 256;"
                     :: "r"(smem_u32(s_tmem)) : "memory");
        asm volatile("tcgen05.relinquish_alloc_permit.cta_group::1.sync.aligned;");
    }
    __syncthreads();
    uint32_t tmem = s_tmem[0];
    uint32_t mb[2] = { smem_u32(&s_mbar[0]), smem_u32(&s_mbar[1]) };

    int nch = K >> 6;
    #define TGLOAD(stage, k0) do {                                                 \
        uint32_t s0 = sbase + (stage)*STG;                                         \
        _Pragma("unroll")                                                          \
        for (int j = 0; j < 24; j++){                                              \
            int i = tid + j*256;                                                   \
            uint32_t dst; const __nv_bfloat16* gp;                                 \
            if (i < 2048){                                                         \
                int half = i >> 10, idx = i & 1023;                                \
                int r = idx >> 3, ch = idx & 7;                                    \
                gp = (half ? Alo : Ahi) + (size_t)(m0 + r)*lda + (k0) + ch*8;      \
                dst = s0 + half*16384u + sw128((uint32_t)(r*128 + ch*16));         \
            } else {                                                               \
                int ii = i - 2048;                                                 \
                int half = ii >> 11, idx = ii & 2047;                              \
                int r = idx >> 3, ch = idx & 7;                                    \
                gp = (half ? Blo : Bhi) + (size_t)(nbase + r)*K + (k0) + ch*8;     \
                dst = s0 + 32768u + half*32768u + sw128((uint32_t)(r*128 + ch*16));\
            }                                                                      \
            CP_ASYNC16(dst, gp);                                                   \
        }                                                                          \
    } while(0)

    TGLOAD(0, 0);
    CP_COMMIT();
    uint32_t ph[2] = {0u, 0u};

    for (int c = 0; c < nch; c++){
        if (c + 1 < nch){
            int s2 = (c+1) & 1;
            if (c >= 1){
                asm volatile("{\n\t.reg .pred P;\n\tWL_%=:\n\t"
                    "mbarrier.try_wait.parity.acquire.cta.shared::cta.b64 P, [%0], %1, 0x989680;\n\t"
                    "@P bra.uni WD_%=;\n\tbra.uni WL_%=;\n\tWD_%=:\n\t}"
                    :: "r"(mb[s2]), "r"(ph[s2]) : "memory");
                ph[s2] ^= 1u;
            }
            TGLOAD(s2, (c+1)*64);
            CP_COMMIT();
            CP_WAIT(1);
        } else {
            CP_WAIT(0);
        }
        __syncthreads();
        FENCE_ASYNC();
        if (wid == 0){
            uint32_t pe;
            asm volatile("{\n\t.reg .pred p;\n\telect.sync _|p, 0xFFFFFFFF;\n\tselp.b32 %0, 1, 0, p;\n\t}" : "=r"(pe));
            if (pe){
                uint32_t base = sbase + (c&1)*STG;
                uint64_t ah = smem_desc(base);
                uint64_t al = smem_desc(base + 16384u);
                uint64_t bh = smem_desc(base + 32768u);
                uint64_t bl = smem_desc(base + 65536u);
                #pragma unroll
                for (int ks = 0; ks < 4; ks++){
                    uint32_t a0 = (c > 0 || ks > 0) ? 1u : 0u;
                    asm volatile("{\n\t.reg .pred p;\n\tsetp.ne.u32 p, %5, 0;\n\t"
                        "tcgen05.mma.cta_group::1.kind::f16 [%0], %1, %2, %3, {%4,%4,%4,%4}, p;\n\t}"
                        :: "r"(tmem), "l"(ah + ks*2), "l"(bh + ks*2), "r"(TG_IDESC), "r"(0u), "r"(a0) : "memory");
                    asm volatile("{\n\t.reg .pred p;\n\tsetp.ne.u32 p, %5, 0;\n\t"
                        "tcgen05.mma.cta_group::1.kind::f16 [%0], %1, %2, %3, {%4,%4,%4,%4}, p;\n\t}"
                        :: "r"(tmem), "l"(al + ks*2), "l"(bh + ks*2), "r"(TG_IDESC), "r"(0u), "r"(1u) : "memory");
                    asm volatile("{\n\t.reg .pred p;\n\tsetp.ne.u32 p, %5, 0;\n\t"
                        "tcgen05.mma.cta_group::1.kind::f16 [%0], %1, %2, %3, {%4,%4,%4,%4}, p;\n\t}"
                        :: "r"(tmem), "l"(ah + ks*2), "l"(bl + ks*2), "r"(TG_IDESC), "r"(0u), "r"(1u) : "memory");
                }
                asm volatile("tcgen05.commit.cta_group::1.mbarrier::arrive::one.shared::cluster.b64 [%0];"
                             :: "r"(mb[c&1]) : "memory");
            }
        }
    }
    {
        int s = (nch-1) & 1;
        asm volatile("{\n\t.reg .pred P;\n\tWL_%=:\n\t"
            "mbarrier.try_wait.parity.acquire.cta.shared::cta.b64 P, [%0], %1, 0x989680;\n\t"
            "@P bra.uni WD_%=;\n\tbra.uni WL_%=;\n\tWD_%=:\n\t}"
            :: "r"(mb[s]), "r"(ph[s]) : "memory");
    }
    asm volatile("tcgen05.fence::after_thread_sync;" ::: "memory");

    float* stg = (float*)smp;
    int cb = (wid >> 2) * 128;
    int row = (wid & 3) * 32 + lane;
    #pragma unroll
    for (int r = 0; r < 4; r++){
        uint32_t dreg[32];
        asm volatile("tcgen05.ld.sync.aligned.32x32b.x32.b32 "
            "{%0,%1,%2,%3,%4,%5,%6,%7,%8,%9,%10,%11,%12,%13,%14,%15,"
            "%16,%17,%18,%19,%20,%21,%22,%23,%24,%25,%26,%27,%28,%29,%30,%31}, [%32];"
            : "=r"(dreg[0]),"=r"(dreg[1]),"=r"(dreg[2]),"=r"(dreg[3]),"=r"(dreg[4]),"=r"(dreg[5]),"=r"(dreg[6]),"=r"(dreg[7]),
              "=r"(dreg[8]),"=r"(dreg[9]),"=r"(dreg[10]),"=r"(dreg[11]),"=r"(dreg[12]),"=r"(dreg[13]),"=r"(dreg[14]),"=r"(dreg[15]),
              "=r"(dreg[16]),"=r"(dreg[17]),"=r"(dreg[18]),"=r"(dreg[19]),"=r"(dreg[20]),"=r"(dreg[21]),"=r"(dreg[22]),"=r"(dreg[23]),
              "=r"(dreg[24]),"=r"(dreg[25]),"=r"(dreg[26]),"=r"(dreg[27]),"=r"(dreg[28]),"=r"(dreg[29]),"=r"(dreg[30]),"=r"(dreg[31])
            : "r"(tmem + cb + r*32));
        asm volatile("tcgen05.wait::ld.sync.aligned;" ::: "memory");
        #pragma unroll
        for (int j = 0; j < 32; j++)
            stg[row*261 + cb + r*32 + j] = __uint_as_float(dreg[j]);
    }
    __syncthreads();
    if (wid == 0)
        asm volatile("tcgen05.dealloc.cta_group::1.sync.aligned.b32 %0, 256;" :: "r"(tmem));

    for (int i = tid; i < 8192; i += 256){
        int r = i >> 6, q = (i & 63) * 4;
        int m = m0 + r, n = nbase + q;
        if (n + 3 < N){
            float v0 = stg[r*261 + q]     + bias[n];
            float v1 = stg[r*261 + q + 1] + bias[n+1];
            float v2 = stg[r*261 + q + 2] + bias[n+2];
            float v3 = stg[r*261 + q + 3] + bias[n+3];
            if (act == 1){
                v0 = 0.5f*v0*(1.f + erff(v0*0.70710678118654752f));
                v1 = 0.5f*v1*(1.f + erff(v1*0.70710678118654752f));
                v2 = 0.5f*v2*(1.f + erff(v2*0.70710678118654752f));
                v3 = 0.5f*v3*(1.f + erff(v3*0.70710678118654752f));
            }
            if (Chi){
                __nv_bfloat16 h0,l0,h1,l1,h2,l2,h3,l3;
                split2(v0,h0,l0); split2(v1,h1,l1); split2(v2,h2,l2); split2(v3,h3,l3);
                __nv_bfloat162 hp0; hp0.x=h0; hp0.y=h1;
                __nv_bfloat162 hp1; hp1.x=h2; hp1.y=h3;
                __nv_bfloat162 lp0; lp0.x=l0; lp0.y=l1;
                __nv_bfloat162 lp1; lp1.x=l2; lp1.y=l3;
                *(__nv_bfloat162*)(Chi + (size_t)m*N + n)     = hp0;
                *(__nv_bfloat162*)(Chi + (size_t)m*N + n + 2) = hp1;
                *(__nv_bfloat162*)(Clo + (size_t)m*N + n)     = lp0;
                *(__nv_bfloat162*)(Clo + (size_t)m*N + n + 2) = lp1;
            } else {
                if (resid){
                    float4 rp = *(const float4*)(resid + (size_t)m*N + n);
                    v0 += rp.x; v1 += rp.y; v2 += rp.z; v3 += rp.w;
                }
                float4 o = make_float4(v0, v1, v2, v3);
                *(float4*)(C + (size_t)m*N + n) = o;
            }
        } else if (n < N){
            #pragma unroll
            for (int j = 0; j < 4; j++){
                int nn = n + j;
                if (nn < N){
                    float v = stg[r*261 + q + j] + bias[nn];
                    if (act == 1) v = 0.5f*v*(1.f + erff(v*0.70710678118654752f));
                    if (Chi){
                        __nv_bfloat16 h0,l0; split2(v,h0,l0);
                        Chi[(size_t)m*N + nn] = h0; Clo[(size_t)m*N + nn] = l0;
                    } else {
                        if (resid) v += resid[(size_t)m*N + nn];
                        C[(size_t)m*N + nn] = v;
                    }
                }
            }
        }
    }
    #undef TGLOAD

#else
    #define AST 40
    #define T_ELEM (128*AST)
    #define S_ELEM (4*T_ELEM)
    __nv_bfloat16* sm = (__nv_bfloat16*)dyn;
    uint32_t sb = smem_u32(sm);
    int wm = (wid & 1) * 64;
    int wn = (wid >> 1) * 32;
    int nchunks = K >> 5;

    for (int half = 0; half < 2; half++){
        int n0 = nbase + half*128;
        float acc[16][4];
        #pragma unroll
        for (int i = 0; i < 16; i++){
            acc[i][0]=0.f; acc[i][1]=0.f; acc[i][2]=0.f; acc[i][3]=0.f;
        }
        #define PREFETCH(stage, k0) do {                                               \
            uint32_t s0 = sb + (stage)*(S_ELEM*2);                                     \
            _Pragma("unroll")                                                          \
            for (int j = 0; j < 8; j++){                                               \
                int i = tid + j*256;                                                   \
                int tile = i >> 9, r = (i >> 2) & 127, ch = i & 3;                     \
                const __nv_bfloat16* gp;                                               \
                if      (tile == 0) gp = Ahi + (size_t)(m0+r)*lda + (k0) + ch*8;       \
                else if (tile == 1) gp = Alo + (size_t)(m0+r)*lda + (k0) + ch*8;       \
                else if (tile == 2) gp = Bhi + (size_t)(n0+r)*K   + (k0) + ch*8;       \
                else                gp = Blo + (size_t)(n0+r)*K   + (k0) + ch*8;       \
                uint32_t dst = s0 + tile*(T_ELEM*2) + r*(AST*2) + ch*16;               \
                CP_ASYNC16(dst, gp);                                                   \
            }                                                                          \
        } while(0)
        PREFETCH(0, 0);
        CP_COMMIT();
        for (int c = 0; c < nchunks; c++){
            if (c + 1 < nchunks){
                PREFETCH((c+1)&1, (c+1)*32);
                CP_COMMIT();
                CP_WAIT(1);
            } else CP_WAIT(0);
            __syncthreads();
            __nv_bfloat16* st  = sm + (c&1)*S_ELEM;
            __nv_bfloat16* sAh = st;
            __nv_bfloat16* sAl = st + T_ELEM;
            __nv_bfloat16* sBh = st + 2*T_ELEM;
            __nv_bfloat16* sBl = st + 3*T_ELEM;
            #pragma unroll
            for (int ks = 0; ks < 2; ks++){
                int kb = ks * 16 + (lane >> 4) * 8;
                int rr = lane & 15;
                uint32_t ah[4][4], al[4][4], bfr[2][4];
                #pragma unroll
                for (int mi = 0; mi < 4; mi++){
                    uint32_t ad = smem_u32(&sAh[(wm + mi*16 + rr)*AST + kb]);
                    LDSM4(ah[mi][0], ah[mi][1], ah[mi][2], ah[mi][3], ad);
                }
                #pragma unroll
                for (int mi = 0; mi < 4; mi++){
                    uint32_t ad = smem_u32(&sAl[(wm + mi*16 + rr)*AST + kb]);
                    LDSM4(al[mi][0], al[mi][1], al[mi][2], al[mi][3], ad);
                }
                #pragma unroll
                for (int nj = 0; nj < 2; nj++){
                    uint32_t ad = smem_u32(&sBh[(wn + nj*16 + rr)*AST + kb]);
                    LDSM4(bfr[nj][0], bfr[nj][1], bfr[nj][2], bfr[nj][3], ad);
                }
                #pragma unroll
                for (int mi = 0; mi < 4; mi++)
                    #pragma unroll
                    for (int ni = 0; ni < 4; ni++){
                        uint32_t b0 = bfr[ni>>1][(ni&1)];
                        uint32_t b1 = bfr[ni>>1][(ni&1)+2];
                        MMA16816(acc[mi*4+ni], ah[mi], b0, b1);
                        MMA16816(acc[mi*4+ni], al[mi], b0, b1);
                    }
                #pragma unroll
                for (int nj = 0; nj < 2; nj++){
                    uint32_t ad = smem_u32(&sBl[(wn + nj*16 + rr)*AST + kb]);
                    LDSM4(bfr[nj][0], bfr[nj][1], bfr[nj][2], bfr[nj][3], ad);
                }
                #pragma unroll
                for (int mi = 0; mi < 4; mi++)
                    #pragma unroll
                    for (int ni = 0; ni < 4; ni++){
                        uint32_t b0 = bfr[ni>>1][(ni&1)];
                        uint32_t b1 = bfr[ni>>1][(ni&1)+2];
                        MMA16816(acc[mi*4+ni], ah[mi], b0, b1);
                    }
            }
            __syncthreads();
        }
        #pragma unroll
        for (int mi = 0; mi < 4; mi++){
            #pragma unroll
            for (int ni = 0; ni < 4; ni++){
                float* ac = acc[mi*4+ni];
                int n = n0 + wn + ni*8 + (lane & 3)*2;
                if (n + 1 < N){
                    float b0 = bias[n], b1 = bias[n+1];
                    #pragma unroll
                    for (int hf = 0; hf < 2; hf++){
                        int m = m0 + wm + mi*16 + (lane >> 2) + hf*8;
                        float v0 = ac[hf*2]   + b0;
                        float v1 = ac[hf*2+1] + b1;
                        if (act == 1){
                            v0 = 0.5f*v0*(1.f + erff(v0*0.70710678118654752f));
                            v1 = 0.5f*v1*(1.f + erff(v1*0.70710678118654752f));
                        }
                        if (Chi){
                            __nv_bfloat16 h0,l0,h1,l1;
                            split2(v0,h0,l0); split2(v1,h1,l1);
                            __nv_bfloat162 hp, lp;
                            hp.x=h0; hp.y=h1; lp.x=l0; lp.y=l1;
                            *(__nv_bfloat162*)(Chi + (size_t)m*N + n) = hp;
                            *(__nv_bfloat162*)(Clo + (size_t)m*N + n) = lp;
                        } else {
                            if (resid){
                                float2 rp = *(const float2*)(resid + (size_t)m*N + n);
                                v0 += rp.x; v1 += rp.y;
                            }
                            float2 o = make_float2(v0, v1);
                            *(float2*)(C + (size_t)m*N + n) = o;
                        }
                    }
                } else if (n < N){
                    float b0 = bias[n];
                    #pragma unroll
                    for (int hf = 0; hf < 2; hf++){
                        int m = m0 + wm + mi*16 + (lane >> 2) + hf*8;
                        float v0 = ac[hf*2] + b0;
                        if (act == 1) v0 = 0.5f*v0*(1.f + erff(v0*0.70710678118654752f));
                        if (Chi){
                            __nv_bfloat16 h0,l0; split2(v0,h0,l0);
                            Chi[(size_t)m*N + n] = h0;
                            Clo[(size_t)m*N + n] = l0;
                        } else {
                            if (resid) v0 += resid[(size_t)m*N + n];
                            C[(size_t)m*N + n] = v0;
                        }
                    }
                }
            }
        }
        __syncthreads();
        #undef PREFETCH
    }
#endif
}

// ---------------- timestep embedding features ----------------
__global__ void k_tfeat(const float* __restrict__ t, float* __restrict__ out){
    int i = blockIdx.x*blockDim.x + threadIdx.x;
    if (i >= NB*NCD) return;
    int b = i / NCD, j = i % NCD;
    const int half = NCD/2;
    int idx = (j < half) ? j : (j - half);
    float f   = expf(-9.210340371976184f * (float)idx / (float)half);
    float ang = t[b] * f;
    out[i] = (j < half) ? sinf(ang) : cosf(ang);
}

// ---------------- small GEMM (rows = NB only) ----------------
__global__ __launch_bounds__(256) void k_sgemm2(const float* __restrict__ X,
                                                const float* __restrict__ W,
                                                const float* __restrict__ bias,
                                                float* __restrict__ Y,
                                                int K, int N, int act){
    __shared__ float red[2][4][65];
    int lane = threadIdx.x & 63;
    int slice = threadIdx.x >> 6;
    int n = blockIdx.x*64 + lane;
    int kps = K >> 2;
    float a0 = 0.f, a1 = 0.f;
    if (n < N){
        const float* x0 = X;
        const float* x1 = X + K;
        int k0 = slice*kps, k1 = k0 + kps;
        #pragma unroll 4
        for (int k = k0; k < k1; k++){
            float w = W[(size_t)k*N + n];
            a0 += x0[k]*w; a1 += x1[k]*w;
        }
    }
    red[0][slice][lane] = a0;
    red[1][slice][lane] = a1;
    __syncthreads();
    if (threadIdx.x < 128){
        int bb = threadIdx.x >> 6, l = threadIdx.x & 63;
        float s = red[bb][0][l] + red[bb][1][l] + red[bb][2][l] + red[bb][3][l];
        int nn = blockIdx.x*64 + l;
        if (nn < N){
            s += bias[nn];
            if (act == 1) s = s / (1.f + expf(-s));
            Y[(size_t)bb*N + nn] = s;
        }
    }
}

// ---------------- batched adaLN GEMM: all layers at once (blockIdx.y = layer) --------
__global__ __launch_bounds__(256) void k_sgemm2b(const float* __restrict__ X,
                                                 const float* __restrict__ Wbase,
                                                 const float* __restrict__ bbase,
                                                 float* __restrict__ Ybase){
    __shared__ float red[2][4][65];
    int l = blockIdx.y;
    const float* W = Wbase + (size_t)l*ND*2*ND;
    const float* bias = bbase + (size_t)l*2*ND;
    float* Y = Ybase + (size_t)l*NB*2*ND;
    const int K = ND, N = 2*ND;
    int lane = threadIdx.x & 63;
    int slice = threadIdx.x >> 6;
    int n = blockIdx.x*64 + lane;
    int kps = K >> 2;
    float a0 = 0.f, a1 = 0.f;
    {
        const float* x0 = X;
        const float* x1 = X + K;
        int k0 = slice*kps, k1 = k0 + kps;
        #pragma unroll 4
        for (int k = k0; k < k1; k++){
            float w = W[(size_t)k*N + n];
            a0 += x0[k]*w; a1 += x1[k]*w;
        }
    }
    red[0][slice][lane] = a0;
    red[1][slice][lane] = a1;
    __syncthreads();
    if (threadIdx.x < 128){
        int bb = threadIdx.x >> 6, ll = threadIdx.x & 63;
        float s = red[bb][0][ll] + red[bb][1][ll] + red[bb][2][ll] + red[bb][3][ll];
        int nn = blockIdx.x*64 + ll;
        s += bias[nn];
        Y[(size_t)bb*N + nn] = s;
    }
}

// ---------------- rope tables ----------------
__global__ void k_rope_tab(){
    int i = blockIdx.x*blockDim.x + threadIdx.x;
    if (i >= NT*(NDH/2)) return;
    int t = i >> 5, j = i & 31;
    float freq = (float)pow(10000.0, -(double)(2*j) / (double)NDH);
    float ang  = (float)t * freq;
    g_rc[i] = cosf(ang);
    g_rs[i] = sinf(ang);
}

// ---------------- LayerNorm (+adaLN), split bf16 hi/lo output ----------------
__global__ __launch_bounds__(256) void k_ln(const float* __restrict__ X,
                                            const float* __restrict__ ss,
                                            __nv_bfloat16* __restrict__ Yh,
                                            __nv_bfloat16* __restrict__ Yl){
    int row = blockIdx.x;
    int b = row / NT;
    const float4* x4 = (const float4*)(X + (size_t)row*ND);
    int tid = threadIdx.x;
    float4 v = x4[tid];
    float s = v.x+v.y+v.z+v.w;
    float q = v.x*v.x+v.y*v.y+v.z*v.z+v.w*v.w;
    #pragma unroll
    for (int o=16;o;o>>=1){ s += __shfl_xor_sync(0xffffffffu,s,o); q += __shfl_xor_sync(0xffffffffu,q,o); }
    __shared__ float shs[8], shq[8];
    __shared__ float smean, srstd;
    int w = tid>>5;
    if ((tid&31)==0){ shs[w]=s; shq[w]=q; }
    __syncthreads();
    if (tid==0){
        float S=0.f,Q=0.f;
        #pragma unroll
        for (int k=0;k<8;k++){ S+=shs[k]; Q+=shq[k]; }
        float mean = S*(1.f/ND);
        float var  = Q*(1.f/ND) - mean*mean;
        smean = mean; srstd = rsqrtf(var + LNEPS);
    }
    __syncthreads();
    float mean = smean, r = srstd;
    int n0 = tid*4;
    float o[4];
    o[0]=(v.x-mean)*r; o[1]=(v.y-mean)*r; o[2]=(v.z-mean)*r; o[3]=(v.w-mean)*r;
    if (ss){
        const float* sc = ss + (size_t)b*2*ND;
        const float* sh = sc + ND;
        #pragma unroll
        for (int j=0;j<4;j++) o[j] = o[j]*(1.f+sc[n0+j]) + sh[n0+j];
    }
    __nv_bfloat16 hh[4], ll[4];
    #pragma unroll
    for (int j=0;j<4;j++) split2(o[j], hh[j], ll[j]);
    *(uint2*)(Yh + (size_t)row*ND + n0) = *(uint2*)hh;
    *(uint2*)(Yl + (size_t)row*ND + n0) = *(uint2*)ll;
}

// ---------------- attention v3b (unchanged from R12) ----------------
#define QST 72
#define AT_Q (128*QST)
#define AT_K (64*QST)
#define ATT_SMEM ((2*AT_Q + 4*AT_K)*2)
__global__ __launch_bounds__(256) void k_attn(const float* __restrict__ qkv,
                                              __nv_bfloat16* __restrict__ Oh,
                                              __nv_bfloat16* __restrict__ Ol){
    extern __shared__ __nv_bfloat16 smb[];
    __nv_bfloat16* sQh = smb;
    __nv_bfloat16* sQl = smb + AT_Q;
    __nv_bfloat16* sKh = smb + 2*AT_Q;
    __nv_bfloat16* sKl = smb + 2*AT_Q + AT_K;
    __nv_bfloat16* sVh = smb + 2*AT_Q + 2*AT_K;
    __nv_bfloat16* sVl = smb + 2*AT_Q + 3*AT_K;
    int qt = blockIdx.x, h = blockIdx.y, b = blockIdx.z;
    int tid = threadIdx.x, lane = tid & 31, w = tid >> 5;
    int q0 = qt * 128;
    int wr = w * 16;
    const float scale = 0.125f;

    for (int i = tid; i < 128*32; i += 256){
        int jp = i & 31, r = i >> 5;
        int tok = q0 + r;
        size_t g = (((size_t)(b*NT + tok)*3 + 0)*NH + h)*NDH + 2*jp;
        float x1 = qkv[g], x2 = qkv[g+1];
        float cs = g_rc[tok*32 + jp], sn = g_rs[tok*32 + jp];
        float y1 = (x1*cs - x2*sn) * scale;
        float y2 = (x1*sn + x2*cs) * scale;
        __nv_bfloat16 h1,l1,h2,l2;
        split2(y1,h1,l1); split2(y2,h2,l2);
        __nv_bfloat162 hp; hp.x=h1; hp.y=h2;
        __nv_bfloat162 lp; lp.x=l1; lp.y=l2;
        *(__nv_bfloat162*)&sQh[r*QST + 2*jp] = hp;
        *(__nv_bfloat162*)&sQl[r*QST + 2*jp] = lp;
    }
    __syncthreads();

    float accO[8][4];
    #pragma unroll
    for (int i=0;i<8;i++){ accO[i][0]=0.f; accO[i][1]=0.f; accO[i][2]=0.f; accO[i][3]=0.f; }
    float m_[2] = {-1e30f, -1e30f};
    float l_[2] = {0.f, 0.f};

    int ktiles = min(8, 2*qt + 2);
    for (int jt = 0; jt < ktiles; jt++){
        for (int i = tid; i < 64*32; i += 256){
            int jp = i & 31, r = i >> 5;
            int tok = NT - NWIN + jt*64 + r;
            size_t gk = (((size_t)(b*NT + tok)*3 + 1)*NH + h)*NDH + 2*jp;
            float x1 = qkv[gk], x2 = qkv[gk+1];
            float cs = g_rc[tok*32 + jp], sn = g_rs[tok*32 + jp];
            float y1 = x1*cs - x2*sn;
            float y2 = x1*sn + x2*cs;
            __nv_bfloat16 h1,l1,h2,l2;
            split2(y1,h1,l1); split2(y2,h2,l2);
            __nv_bfloat162 hp; hp.x=h1; hp.y=h2;
            __nv_bfloat162 lp; lp.x=l1; lp.y=l2;
            *(__nv_bfloat162*)&sKh[r*QST + 2*jp] = hp;
            *(__nv_bfloat162*)&sKl[r*QST + 2*jp] = lp;
            float v1 = qkv[gk + NH*NDH], v2 = qkv[gk + NH*NDH + 1];
            __nv_bfloat16 vh1,vl1,vh2,vl2;
            split2(v1,vh1,vl1); split2(v2,vh2,vl2);
            sVh[(2*jp)*QST + r]   = vh1;
            sVh[(2*jp+1)*QST + r] = vh2;
            sVl[(2*jp)*QST + r]   = vl1;
            sVl[(2*jp+1)*QST + r] = vl2;
        }
        __syncthreads();

        float S[8][4];
        #pragma unroll
        for (int i=0;i<8;i++){ S[i][0]=0.f; S[i][1]=0.f; S[i][2]=0.f; S[i][3]=0.f; }
        int kb0 = (lane >> 4) * 8;
        int rr = lane & 15;
        #pragma unroll
        for (int s = 0; s < 4; s++){
            int kb = s*16 + kb0;
            uint32_t qh[4], ql[4], bfr[4][4];
            LDSM4(qh[0],qh[1],qh[2],qh[3], smem_u32(&sQh[(wr + rr)*QST + kb]));
            LDSM4(ql[0],ql[1],ql[2],ql[3], smem_u32(&sQl[(wr + rr)*QST + kb]));
            #pragma unroll
            for (int nj = 0; nj < 4; nj++)
                LDSM4(bfr[nj][0],bfr[nj][1],bfr[nj][2],bfr[nj][3],
                      smem_u32(&sKh[(nj*16 + rr)*QST + kb]));
            #pragma unroll
            for (int ni = 0; ni < 8; ni++){
                uint32_t b0 = bfr[ni>>1][ni&1], b1 = bfr[ni>>1][(ni&1)+2];
                MMA16816(S[ni], qh, b0, b1);
                MMA16816(S[ni], ql, b0, b1);
            }
            #pragma unroll
            for (int nj = 0; nj < 4; nj++)
                LDSM4(bfr[nj][0],bfr[nj][1],bfr[nj][2],bfr[nj][3],
                      smem_u32(&sKl[(nj*16 + rr)*QST + kb]));
            #pragma unroll
            for (int ni = 0; ni < 8; ni++){
                uint32_t b0 = bfr[ni>>1][ni&1], b1 = bfr[ni>>1][(ni&1)+2];
                MMA16816(S[ni], qh, b0, b1);
            }
        }

        if (qt < 4 && jt >= 2*qt){
            int r0 = q0 + wr + (lane >> 2);
            int cbase = jt*64 + 2*(lane & 3);
            #pragma unroll
            for (int ni = 0; ni < 8; ni++){
                int cg = cbase + ni*8;
                if (cg     > r0    ) S[ni][0] = -1e30f;
                if (cg + 1 > r0    ) S[ni][1] = -1e30f;
                if (cg     > r0 + 8) S[ni][2] = -1e30f;
                if (cg + 1 > r0 + 8) S[ni][3] = -1e30f;
            }
        }

        float mx0 = -1e30f, mx1 = -1e30f;
        #pragma unroll
        for (int ni = 0; ni < 8; ni++){
            mx0 = fmaxf(mx0, fmaxf(S[ni][0], S[ni][1]));
            mx1 = fmaxf(mx1, fmaxf(S[ni][2], S[ni][3]));
        }
        mx0 = fmaxf(mx0, __shfl_xor_sync(0xffffffffu, mx0, 1));
        mx0 = fmaxf(mx0, __shfl_xor_sync(0xffffffffu, mx0, 2));
        mx1 = fmaxf(mx1, __shfl_xor_sync(0xffffffffu, mx1, 1));
        mx1 = fmaxf(mx1, __shfl_xor_sync(0xffffffffu, mx1, 2));
        float mn0 = fmaxf(m_[0], mx0), mn1 = fmaxf(m_[1], mx1);
        float ls0 = 0.f, ls1 = 0.f;
        #pragma unroll
        for (int ni = 0; ni < 8; ni++){
            S[ni][0] = fexp(S[ni][0] - mn0); ls0 += S[ni][0];
            S[ni][1] = fexp(S[ni][1] - mn0); ls0 += S[ni][1];
            S[ni][2] = fexp(S[ni][2] - mn1); ls1 += S[ni][2];
            S[ni][3] = fexp(S[ni][3] - mn1); ls1 += S[ni][3];
        }
        ls0 += __shfl_xor_sync(0xffffffffu, ls0, 1);
        ls0 += __shfl_xor_sync(0xffffffffu, ls0, 2);
        ls1 += __shfl_xor_sync(0xffffffffu, ls1, 1);
        ls1 += __shfl_xor_sync(0xffffffffu, ls1, 2);
        float al0 = fexp(m_[0] - mn0), al1 = fexp(m_[1] - mn1);
        l_[0] = l_[0]*al0 + ls0;  m_[0] = mn0;
        l_[1] = l_[1]*al1 + ls1;  m_[1] = mn1;
        #pragma unroll
        for (int ni = 0; ni < 8; ni++){
            accO[ni][0] *= al0; accO[ni][1] *= al0;
            accO[ni][2] *= al1; accO[ni][3] *= al1;
        }

        uint32_t pa[8], pb[8], qa[8], qb[8];
        #pragma unroll
        for (int ni = 0; ni < 8; ni++){
            __nv_bfloat16 h0,l0,h1,l1;
            split2(S[ni][0], h0, l0); split2(S[ni][1], h1, l1);
            __nv_bfloat162 hp; hp.x=h0; hp.y=h1;
            __nv_bfloat162 lp; lp.x=l0; lp.y=l1;
            pa[ni] = *(uint32_t*)&hp; qa[ni] = *(uint32_t*)&lp;
            split2(S[ni][2], h0, l0); split2(S[ni][3], h1, l1);
            hp.x=h0; hp.y=h1; lp.x=l0; lp.y=l1;
            pb[ni] = *(uint32_t*)&hp; qb[ni] = *(uint32_t*)&lp;
        }

        #pragma unroll
        for (int s = 0; s < 4; s++){
            int kb = s*16 + kb0;
            uint32_t Ah[4] = { pa[2*s], pb[2*s], pa[2*s+1], pb[2*s+1] };
            uint32_t Al[4] = { qa[2*s], qb[2*s], qa[2*s+1], qb[2*s+1] };
            uint32_t bfr[4][4];
            #pragma unroll
            for (int nj = 0; nj < 4; nj++)
                LDSM4(bfr[nj][0],bfr[nj][1],bfr[nj][2],bfr[nj][3],
                      smem_u32(&sVh[(nj*16 + rr)*QST + kb]));
            #pragma unroll
            for (int ni = 0; ni < 8; ni++){
                uint32_t b0 = bfr[ni>>1][ni&1], b1 = bfr[ni>>1][(ni&1)+2];
                MMA16816(accO[ni], Ah, b0, b1);
                MMA16816(accO[ni], Al, b0, b1);
            }
            #pragma unroll
            for (int nj = 0; nj < 4; nj++)
                LDSM4(bfr[nj][0],bfr[nj][1],bfr[nj][2],bfr[nj][3],
                      smem_u32(&sVl[(nj*16 + rr)*QST + kb]));
            #pragma unroll
            for (int ni = 0; ni < 8; ni++){
                uint32_t b0 = bfr[ni>>1][ni&1], b1 = bfr[ni>>1][(ni&1)+2];
                MMA16816(accO[ni], Ah, b0, b1);
            }
        }
        __syncthreads();
    }

    float inv0 = 1.f / l_[0], inv1 = 1.f / l_[1];
    int r0 = q0 + wr + (lane >> 2);
    int cb = 2*(lane & 3);
    #pragma unroll
    for (int ni = 0; ni < 8; ni++){
        int d = ni*8 + cb;
        {
            float v0 = accO[ni][0]*inv0, v1 = accO[ni][1]*inv0;
            __nv_bfloat16 h0,l0,h1,l1;
            split2(v0,h0,l0); split2(v1,h1,l1);
            __nv_bfloat162 hp; hp.x=h0; hp.y=h1;
            __nv_bfloat162 lp; lp.x=l0; lp.y=l1;
            size_t idx = (((size_t)(b*NT + r0))*NH + h)*NDH + d;
            *(__nv_bfloat162*)(Oh + idx) = hp;
            *(__nv_bfloat162*)(Ol + idx) = lp;
        }
        {
            float v0 = accO[ni][2]*inv1, v1 = accO[ni][3]*inv1;
            __nv_bfloat16 h0,l0,h1,l1;
            split2(v0,h0,l0); split2(v1,h1,l1);
            __nv_bfloat162 hp; hp.x=h0; hp.y=h1;
            __nv_bfloat162 lp; lp.x=l0; lp.y=l1;
            size_t idx = (((size_t)(b*NT + r0 + 8))*NH + h)*NDH + d;
            *(__nv_bfloat162*)(Oh + idx) = hp;
            *(__nv_bfloat162*)(Ol + idx) = lp;
        }
    }
}

// ---------------- orchestration ----------------
extern "C" void kernel_launch(void* const* d_in, const int* in_sizes, int n_in,
                              void* d_out, int out_size){
    (void)in_sizes; (void)n_in; (void)out_size;
    const float* x      = (const float*)d_in[0];
    const float* t      = (const float*)d_in[1];
    const float* W_in   = (const float*)d_in[2];
    const float* b_in   = (const float*)d_in[3];
    const float* Wt1    = (const float*)d_in[4];
    const float* bt1    = (const float*)d_in[5];
    const float* Wt2    = (const float*)d_in[6];
    const float* bt2    = (const float*)d_in[7];
    const float* Wcm    = (const float*)d_in[8];
    const float* bcm    = (const float*)d_in[9];
    const float* ada1_W = (const float*)d_in[10];
    const float* ada1_b = (const float*)d_in[11];
    const float* qkv_W  = (const float*)d_in[12];
    const float* qkv_b  = (const float*)d_in[13];
    const float* attno_W= (const float*)d_in[14];
    const float* attno_b= (const float*)d_in[15];
    const float* ada2_W = (const float*)d_in[16];
    const float* ada2_b = (const float*)d_in[17];
    const float* mlp_W1 = (const float*)d_in[18];
    const float* mlp_b1 = (const float*)d_in[19];
    const float* mlp_W2 = (const float*)d_in[20];
    const float* mlp_b2 = (const float*)d_in[21];
    const float* W_out  = (const float*)d_in[22];
    const float* b_out  = (const float*)d_in[23];

    float *p_h,*p_qkv,*p_ta,*p_tb,*p_cond,*p_ss1,*p_ss2;
    cudaGetSymbolAddress((void**)&p_h,    g_h);
    cudaGetSymbolAddress((void**)&p_qkv,  g_qkv);
    cudaGetSymbolAddress((void**)&p_ta,   g_ta);
    cudaGetSymbolAddress((void**)&p_tb,   g_tb);
    cudaGetSymbolAddress((void**)&p_cond, g_cond);
    cudaGetSymbolAddress((void**)&p_ss1,  g_ss1);
    cudaGetSymbolAddress((void**)&p_ss2,  g_ss2);

    __nv_bfloat16 *p_xh,*p_xl,*p_hnh,*p_hnl,*p_ath,*p_atl,*p_ffh,*p_ffl;
    cudaGetSymbolAddress((void**)&p_xh,  g_xh);
    cudaGetSymbolAddress((void**)&p_xl,  g_xl);
    cudaGetSymbolAddress((void**)&p_hnh, g_hn_h);
    cudaGetSymbolAddress((void**)&p_hnl, g_hn_l);
    cudaGetSymbolAddress((void**)&p_ath, g_at_h);
    cudaGetSymbolAddress((void**)&p_atl, g_at_l);
    cudaGetSymbolAddress((void**)&p_ffh, g_ff_h);
    cudaGetSymbolAddress((void**)&p_ffl, g_ff_l);

    __nv_bfloat16 *w_in_h,*w_in_l,*w_qkv_h,*w_qkv_l,*w_ao_h,*w_ao_l;
    __nv_bfloat16 *w_m1_h,*w_m1_l,*w_m2_h,*w_m2_l,*w_out_h,*w_out_l;
    cudaGetSymbolAddress((void**)&w_in_h,  c_in_hi);
    cudaGetSymbolAddress((void**)&w_in_l,  c_in_lo);
    cudaGetSymbolAddress((void**)&w_qkv_h, c_qkv_hi);
    cudaGetSymbolAddress((void**)&w_qkv_l, c_qkv_lo);
    cudaGetSymbolAddress((void**)&w_ao_h,  c_ao_hi);
    cudaGetSymbolAddress((void**)&w_ao_l,  c_ao_lo);
    cudaGetSymbolAddress((void**)&w_m1_h,  c_m1_hi);
    cudaGetSymbolAddress((void**)&w_m1_l,  c_m1_lo);
    cudaGetSymbolAddress((void**)&w_m2_h,  c_m2_hi);
    cudaGetSymbolAddress((void**)&w_m2_l,  c_m2_lo);
    cudaGetSymbolAddress((void**)&w_out_h, c_out_hi);
    cudaGetSymbolAddress((void**)&w_out_l, c_out_lo);

    cudaFuncSetAttribute(k_tgemm, cudaFuncAttributeMaxDynamicSharedMemorySize, TG_SMEM);
    cudaFuncSetAttribute(k_attn,  cudaFuncAttributeMaxDynamicSharedMemorySize, ATT_SMEM);

    const int M = NB*NT;
    dim3 wblk(32, 8);

    // ---- weight conversion (batched across layers) ----
    k_wconv<<<dim3(ND/32, 128/32, 1), wblk>>>(W_in,  w_in_h,  w_in_l,  NMEL, ND, 128, 0, 0);
    k_wconv<<<dim3(256/32, ND/32, 1), wblk>>>(W_out, w_out_h, w_out_l, ND, NMEL, ND, 0, 0);
    k_wconv<<<dim3(3*ND/32, ND/32, NLAYER), wblk>>>(qkv_W,  w_qkv_h, w_qkv_l, ND, 3*ND, ND,
                                                    (size_t)ND*3*ND, (size_t)3*ND*ND);
    k_wconv<<<dim3(ND/32,   ND/32, NLAYER), wblk>>>(attno_W, w_ao_h, w_ao_l, ND, ND, ND,
                                                    (size_t)ND*ND, (size_t)ND*ND);
    k_wconv<<<dim3(NFF/32,  ND/32, NLAYER), wblk>>>(mlp_W1, w_m1_h, w_m1_l, ND, NFF, ND,
                                                    (size_t)ND*NFF, (size_t)NFF*ND);
    k_wconv<<<dim3(ND/32,  NFF/32, NLAYER), wblk>>>(mlp_W2, w_m2_h, w_m2_l, NFF, ND, NFF,
                                                    (size_t)NFF*ND, (size_t)ND*NFF);

    // ---- timestep conditioning ----
    k_tfeat<<<(NB*NCD+255)/256,256>>>(t, p_ta);
    k_sgemm2<<<NCD/64,256>>>(p_ta, Wt1, bt1, p_tb, NCD, NCD, 1);
    k_sgemm2<<<NCD/64,256>>>(p_tb, Wt2, bt2, p_ta, NCD, NCD, 0);
    k_sgemm2<<<ND/64, 256>>>(p_ta, Wcm, bcm, p_cond, NCD, ND, 1);
    k_rope_tab<<<(NT*32+255)/256,256>>>();

    // ---- all adaLN scale/shift GEMMs, batched across layers (depend only on cond) ----
    k_sgemm2b<<<dim3(2*ND/64, NLAYER), 256>>>(p_cond, ada1_W, ada1_b, p_ss1);
    k_sgemm2b<<<dim3(2*ND/64, NLAYER), 256>>>(p_cond, ada2_W, ada2_b, p_ss2);

    // ---- input projection (padded K = 128) ----
    k_split<<<(M*128)/256, 256>>>(x, p_xh, p_xl);
    k_tgemm<<<dim3(32, 4), 256, TG_SMEM>>>(p_xh, p_xl, 128, w_in_h, w_in_l,
                                           b_in, nullptr, p_h, nullptr, nullptr,
                                           ND, 128, 0);

    for (int l = 0; l < NLAYER; l++){
        k_ln<<<M,256>>>(p_h, p_ss1 + (size_t)l*NB*2*ND, p_hnh, p_hnl);
        k_tgemm<<<dim3(32, 12), 256, TG_SMEM>>>(p_hnh, p_hnl, ND,
                                                w_qkv_h + (size_t)l*3*ND*ND,
                                                w_qkv_l + (size_t)l*3*ND*ND,
                                                qkv_b + (size_t)l*3*ND, nullptr,
                                                p_qkv, nullptr, nullptr,
                                                3*ND, ND, 0);
        k_attn<<<dim3(NT/128, NH, NB), 256, ATT_SMEM>>>(p_qkv, p_ath, p_atl);
        k_tgemm<<<dim3(32, 4), 256, TG_SMEM>>>(p_ath, p_atl, ND,
                                               w_ao_h + (size_t)l*ND*ND,
                                               w_ao_l + (size_t)l*ND*ND,
                                               attno_b + (size_t)l*ND, p_h,
                                               p_h, nullptr, nullptr,
                                               ND, ND, 0);
        k_ln<<<M,256>>>(p_h, p_ss2 + (size_t)l*NB*2*ND, p_hnh, p_hnl);
        k_tgemm<<<dim3(32, 16), 256, TG_SMEM>>>(p_hnh, p_hnl, ND,
                                                w_m1_h + (size_t)l*NFF*ND,
                                                w_m1_l + (size_t)l*NFF*ND,
                                                mlp_b1 + (size_t)l*NFF, nullptr,
                                                nullptr, p_ffh, p_ffl,
                                                NFF, ND, 1);
        k_tgemm<<<dim3(32, 4), 256, TG_SMEM>>>(p_ffh, p_ffl, NFF,
                                               w_m2_h + (size_t)l*ND*NFF,
                                               w_m2_l + (size_t)l*ND*NFF,
                                               mlp_b2 + (size_t)l*ND, p_h,
                                               p_h, nullptr, nullptr,
                                               ND, NFF, 0);
    }

    k_ln<<<M,256>>>(p_h, nullptr, p_hnh, p_hnl);
    k_tgemm<<<dim3(32, 1), 256, TG_SMEM>>>(p_hnh, p_hnl, ND, w_out_h, w_out_l,
                                           b_out, nullptr, (float*)d_out,
                                           nullptr, nullptr, NMEL, ND, 0);
}